// round 1
// baseline (speedup 1.0000x reference)
#include <cuda_runtime.h>
#include <cuda_bf16.h>
#include <math.h>

// Problem constants
#define BATCH 8
#define C_IN 256
#define C_I  128
#define HH   64
#define WW   64
#define NN   4096   // H*W
#define MM   1024   // (H/2)*(W/2)

// Scratch (static __device__ allocations are allowed)
__device__ float d_proj[BATCH][384][NN];      // rows 0..127 theta, 128..255 phi, 256..383 g
__device__ float d_phi_p[BATCH][C_I][MM];
__device__ float d_g_p[BATCH][C_I][MM];
__device__ float d_f[BATCH][NN][MM];          // scores -> softmax in place
__device__ float d_y[BATCH][NN][C_I];
__device__ float d_wy[BATCH][C_IN][NN];
__device__ float d_scale[C_IN];
__device__ float d_shift[C_IN];

// ---------------------------------------------------------------------------
// Kernel 1: fused projections. P[b][o][n] = sum_c W[o][c]*x[b][c][n] + bias
// Tile 64(o) x 64(n), K-step 16, 256 threads, 4x4 micro-tile.
// ---------------------------------------------------------------------------
__global__ void k_proj(const float* __restrict__ x,
                       const float* __restrict__ w_theta, const float* __restrict__ b_theta,
                       const float* __restrict__ w_phi,   const float* __restrict__ b_phi,
                       const float* __restrict__ w_g,     const float* __restrict__ b_g)
{
    const int b  = blockIdx.z;
    const int oT = blockIdx.y * 64;
    const int nT = blockIdx.x * 64;

    const float* Wp; const float* Bp; int oBase;
    if (oT < 128)      { Wp = w_theta; Bp = b_theta; oBase = oT;       }
    else if (oT < 256) { Wp = w_phi;   Bp = b_phi;   oBase = oT - 128; }
    else               { Wp = w_g;     Bp = b_g;     oBase = oT - 256; }

    __shared__ float As[16][65];   // [k][o]
    __shared__ float Bs[16][65];   // [k][n]

    const int tid = threadIdx.x;
    const int tx = tid & 15, ty = tid >> 4;
    float acc[4][4] = {};

    const float* xb = x + (size_t)b * C_IN * NN;

    for (int k0 = 0; k0 < C_IN; k0 += 16) {
        #pragma unroll
        for (int i = 0; i < 4; i++) {
            int idx = tid + i * 256;
            int k = idx & 15, o = idx >> 4;
            As[k][o] = Wp[(size_t)(oBase + o) * C_IN + k0 + k];
        }
        #pragma unroll
        for (int i = 0; i < 4; i++) {
            int idx = tid + i * 256;
            int n = idx & 63, k = idx >> 6;
            Bs[k][n] = xb[(size_t)(k0 + k) * NN + nT + n];
        }
        __syncthreads();
        #pragma unroll
        for (int k = 0; k < 16; k++) {
            float a[4], bb[4];
            #pragma unroll
            for (int i = 0; i < 4; i++) a[i] = As[k][ty * 4 + i];
            #pragma unroll
            for (int j = 0; j < 4; j++) bb[j] = Bs[k][tx * 4 + j];
            #pragma unroll
            for (int i = 0; i < 4; i++)
                #pragma unroll
                for (int j = 0; j < 4; j++) acc[i][j] += a[i] * bb[j];
        }
        __syncthreads();
    }

    #pragma unroll
    for (int i = 0; i < 4; i++) {
        int o = oT + ty * 4 + i;
        float bias = Bp[oBase + ty * 4 + i];
        float* dst = &d_proj[b][o][nT + tx * 4];
        #pragma unroll
        for (int j = 0; j < 4; j++) dst[j] = acc[i][j] + bias;
    }
}

// ---------------------------------------------------------------------------
// Kernel 2: 2x2 maxpool of phi (rows 128..255) and g (rows 256..383)
// ---------------------------------------------------------------------------
__global__ void k_pool()
{
    int idx = blockIdx.x * blockDim.x + threadIdx.x;
    if (idx >= BATCH * C_I * MM) return;
    int m  = idx & (MM - 1);
    int ci = (idx >> 10) & (C_I - 1);
    int b  = idx >> 17;
    int hp = m >> 5, wp = m & 31;
    int n0 = (hp * 2) * WW + wp * 2;

    const float* p = &d_proj[b][128 + ci][0];
    d_phi_p[b][ci][m] = fmaxf(fmaxf(p[n0], p[n0 + 1]), fmaxf(p[n0 + WW], p[n0 + WW + 1]));
    const float* q = &d_proj[b][256 + ci][0];
    d_g_p[b][ci][m]   = fmaxf(fmaxf(q[n0], q[n0 + 1]), fmaxf(q[n0 + WW], q[n0 + WW + 1]));
}

// ---------------------------------------------------------------------------
// Kernel 3: scores f[b][n][m] = sum_k theta[k][n] * phi[k][m]   (K=128)
// ---------------------------------------------------------------------------
__global__ void k_scores()
{
    const int b  = blockIdx.z;
    const int nT = blockIdx.y * 64;
    const int mT = blockIdx.x * 64;

    __shared__ float As[16][65];   // [k][n]
    __shared__ float Bs[16][65];   // [k][m]

    const int tid = threadIdx.x;
    const int tx = tid & 15, ty = tid >> 4;
    float acc[4][4] = {};

    for (int k0 = 0; k0 < C_I; k0 += 16) {
        #pragma unroll
        for (int i = 0; i < 4; i++) {
            int idx = tid + i * 256;
            int n = idx & 63, k = idx >> 6;
            As[k][n] = d_proj[b][k0 + k][nT + n];
        }
        #pragma unroll
        for (int i = 0; i < 4; i++) {
            int idx = tid + i * 256;
            int m = idx & 63, k = idx >> 6;
            Bs[k][m] = d_phi_p[b][k0 + k][mT + m];
        }
        __syncthreads();
        #pragma unroll
        for (int k = 0; k < 16; k++) {
            float a[4], bb[4];
            #pragma unroll
            for (int i = 0; i < 4; i++) a[i] = As[k][ty * 4 + i];
            #pragma unroll
            for (int j = 0; j < 4; j++) bb[j] = Bs[k][tx * 4 + j];
            #pragma unroll
            for (int i = 0; i < 4; i++)
                #pragma unroll
                for (int j = 0; j < 4; j++) acc[i][j] += a[i] * bb[j];
        }
        __syncthreads();
    }

    #pragma unroll
    for (int i = 0; i < 4; i++) {
        float* dst = &d_f[b][nT + ty * 4 + i][mT + tx * 4];
        #pragma unroll
        for (int j = 0; j < 4; j++) dst[j] = acc[i][j];
    }
}

// ---------------------------------------------------------------------------
// Kernel 4: softmax over M=1024, one block (256 threads) per row, in place.
// ---------------------------------------------------------------------------
__global__ void k_softmax()
{
    const int row = blockIdx.x;               // b*NN + n
    float* f = &d_f[0][0][0] + (size_t)row * MM;
    const int t = threadIdx.x;

    __shared__ float red[256];

    float v[4];
    float mx = -1e30f;
    #pragma unroll
    for (int i = 0; i < 4; i++) { v[i] = f[t + i * 256]; mx = fmaxf(mx, v[i]); }

    red[t] = mx; __syncthreads();
    for (int s = 128; s > 0; s >>= 1) {
        if (t < s) red[t] = fmaxf(red[t], red[t + s]);
        __syncthreads();
    }
    mx = red[0]; __syncthreads();

    float sum = 0.f;
    #pragma unroll
    for (int i = 0; i < 4; i++) { v[i] = __expf(v[i] - mx); sum += v[i]; }

    red[t] = sum; __syncthreads();
    for (int s = 128; s > 0; s >>= 1) {
        if (t < s) red[t] += red[t + s];
        __syncthreads();
    }
    float inv = 1.f / red[0];

    #pragma unroll
    for (int i = 0; i < 4; i++) f[t + i * 256] = v[i] * inv;
}

// ---------------------------------------------------------------------------
// Kernel 5: y[b][n][ci] = sum_m P[n][m] * g[ci][m]   (K=1024, NT gemm)
// ---------------------------------------------------------------------------
__global__ void k_y()
{
    const int b   = blockIdx.z;
    const int nT  = blockIdx.y * 64;
    const int ciT = blockIdx.x * 64;

    __shared__ float As[16][65];   // [k][n]
    __shared__ float Bs[16][65];   // [k][ci]

    const int tid = threadIdx.x;
    const int tx = tid & 15, ty = tid >> 4;
    float acc[4][4] = {};

    for (int k0 = 0; k0 < MM; k0 += 16) {
        #pragma unroll
        for (int i = 0; i < 4; i++) {
            int idx = tid + i * 256;
            int k = idx & 15, n = idx >> 4;
            As[k][n] = d_f[b][nT + n][k0 + k];
        }
        #pragma unroll
        for (int i = 0; i < 4; i++) {
            int idx = tid + i * 256;
            int k = idx & 15, ci = idx >> 4;
            Bs[k][ci] = d_g_p[b][ciT + ci][k0 + k];
        }
        __syncthreads();
        #pragma unroll
        for (int k = 0; k < 16; k++) {
            float a[4], bb[4];
            #pragma unroll
            for (int i = 0; i < 4; i++) a[i] = As[k][ty * 4 + i];
            #pragma unroll
            for (int j = 0; j < 4; j++) bb[j] = Bs[k][tx * 4 + j];
            #pragma unroll
            for (int i = 0; i < 4; i++)
                #pragma unroll
                for (int j = 0; j < 4; j++) acc[i][j] += a[i] * bb[j];
        }
        __syncthreads();
    }

    #pragma unroll
    for (int i = 0; i < 4; i++) {
        float* dst = &d_y[b][nT + ty * 4 + i][ciT + tx * 4];
        #pragma unroll
        for (int j = 0; j < 4; j++) dst[j] = acc[i][j];
    }
}

// ---------------------------------------------------------------------------
// Kernel 6: wy[b][c][n] = b_w[c] + sum_k w_w[c][k] * y[b][n][k]   (K=128, NT)
// ---------------------------------------------------------------------------
__global__ void k_wy(const float* __restrict__ w_w, const float* __restrict__ b_w)
{
    const int b  = blockIdx.z;
    const int cT = blockIdx.y * 64;
    const int nT = blockIdx.x * 64;

    __shared__ float As[16][65];   // [k][c]
    __shared__ float Bs[16][65];   // [k][n]

    const int tid = threadIdx.x;
    const int tx = tid & 15, ty = tid >> 4;
    float acc[4][4] = {};

    for (int k0 = 0; k0 < C_I; k0 += 16) {
        #pragma unroll
        for (int i = 0; i < 4; i++) {
            int idx = tid + i * 256;
            int k = idx & 15, c = idx >> 4;
            As[k][c] = w_w[(size_t)(cT + c) * C_I + k0 + k];
        }
        #pragma unroll
        for (int i = 0; i < 4; i++) {
            int idx = tid + i * 256;
            int k = idx & 15, n = idx >> 4;
            Bs[k][n] = d_y[b][nT + n][k0 + k];
        }
        __syncthreads();
        #pragma unroll
        for (int k = 0; k < 16; k++) {
            float a[4], bb[4];
            #pragma unroll
            for (int i = 0; i < 4; i++) a[i] = As[k][ty * 4 + i];
            #pragma unroll
            for (int j = 0; j < 4; j++) bb[j] = Bs[k][tx * 4 + j];
            #pragma unroll
            for (int i = 0; i < 4; i++)
                #pragma unroll
                for (int j = 0; j < 4; j++) acc[i][j] += a[i] * bb[j];
        }
        __syncthreads();
    }

    #pragma unroll
    for (int i = 0; i < 4; i++) {
        int c = cT + ty * 4 + i;
        float bias = b_w[c];
        float* dst = &d_wy[b][c][nT + tx * 4];
        #pragma unroll
        for (int j = 0; j < 4; j++) dst[j] = acc[i][j] + bias;
    }
}

// ---------------------------------------------------------------------------
// Kernel 7: batchnorm statistics per channel (over B*N = 32768 values)
// ---------------------------------------------------------------------------
__global__ void k_bnstat(const float* __restrict__ gamma, const float* __restrict__ beta)
{
    const int c = blockIdx.x;
    const int t = threadIdx.x;
    float s = 0.f, ss = 0.f;
    for (int b = 0; b < BATCH; b++) {
        const float* p = &d_wy[b][c][0];
        for (int i = t; i < NN; i += 256) { float v = p[i]; s += v; ss += v * v; }
    }
    __shared__ float rs[256], rss[256];
    rs[t] = s; rss[t] = ss; __syncthreads();
    for (int k = 128; k > 0; k >>= 1) {
        if (t < k) { rs[t] += rs[t + k]; rss[t] += rss[t + k]; }
        __syncthreads();
    }
    if (t == 0) {
        const float invN = 1.f / (BATCH * NN);
        float mean = rs[0] * invN;
        float var  = rss[0] * invN - mean * mean;
        float istd = rsqrtf(var + 1e-5f);
        float sc = gamma[c] * istd;
        d_scale[c] = sc;
        d_shift[c] = beta[c] - mean * sc;
    }
}

// ---------------------------------------------------------------------------
// Kernel 8: out = BN(wy) + x
// ---------------------------------------------------------------------------
__global__ void k_final(const float* __restrict__ x, float* __restrict__ out)
{
    size_t i = (size_t)blockIdx.x * blockDim.x + threadIdx.x;
    if (i >= (size_t)BATCH * C_IN * NN) return;
    int c = (int)((i >> 12) & (C_IN - 1));
    const float* wy = &d_wy[0][0][0];
    out[i] = wy[i] * d_scale[c] + d_shift[c] + x[i];
}

// ---------------------------------------------------------------------------
extern "C" void kernel_launch(void* const* d_in, const int* in_sizes, int n_in,
                              void* d_out, int out_size)
{
    const float* x       = (const float*)d_in[0];
    const float* w_g     = (const float*)d_in[1];
    const float* b_g     = (const float*)d_in[2];
    const float* w_theta = (const float*)d_in[3];
    const float* b_theta = (const float*)d_in[4];
    const float* w_phi   = (const float*)d_in[5];
    const float* b_phi   = (const float*)d_in[6];
    const float* w_w     = (const float*)d_in[7];
    const float* b_w     = (const float*)d_in[8];
    const float* gamma   = (const float*)d_in[9];
    const float* beta    = (const float*)d_in[10];
    float* out = (float*)d_out;

    k_proj<<<dim3(NN / 64, 384 / 64, BATCH), 256>>>(x, w_theta, b_theta, w_phi, b_phi, w_g, b_g);
    k_pool<<<(BATCH * C_I * MM + 255) / 256, 256>>>();
    k_scores<<<dim3(MM / 64, NN / 64, BATCH), 256>>>();
    k_softmax<<<BATCH * NN, 256>>>();
    k_y<<<dim3(C_I / 64, NN / 64, BATCH), 256>>>();
    k_wy<<<dim3(NN / 64, C_IN / 64, BATCH), 256>>>(w_w, b_w);
    k_bnstat<<<C_IN, 256>>>(gamma, beta);
    k_final<<<(BATCH * C_IN * NN + 255) / 256, 256>>>(x, out);
}

// round 2
// speedup vs baseline: 1.7950x; 1.7950x over previous
#include <cuda_runtime.h>
#include <math.h>

#define BATCH 8
#define C_IN 256
#define C_I  128
#define WW   64
#define NN   4096   // H*W
#define MM   1024   // pooled spatial

// Scratch
__device__ float d_proj[BATCH][384][NN];      // 0..127 theta, 128..255 phi, 256..383 g
__device__ float d_phi_p[BATCH][C_I][MM];
__device__ float d_g_p[BATCH][C_I][MM];
__device__ float d_f[BATCH][NN][MM];
__device__ float d_y[BATCH][C_I][NN];         // NOTE: [ci][n] layout
__device__ float d_wy[BATCH][C_IN][NN];
__device__ float d_scale[C_IN];
__device__ float d_shift[C_IN];

// ---------------------------------------------------------------------------
// Shared 128x128x8 double-buffered SGEMM core. Split 4+4 micro-tile layout:
// thread (tx,ty) owns rows {ty*4..+3, 64+ty*4..+3} x cols {tx*4..+3, 64+tx*4..+3}.
// ---------------------------------------------------------------------------
__device__ __forceinline__ void mma8x8(const float (*As)[132], const float (*Bs)[132],
                                       float acc[8][8], int ty4, int tx4)
{
    #pragma unroll
    for (int k = 0; k < 8; k++) {
        float4 a0 = *(const float4*)&As[k][ty4];
        float4 a1 = *(const float4*)&As[k][64 + ty4];
        float4 b0 = *(const float4*)&Bs[k][tx4];
        float4 b1 = *(const float4*)&Bs[k][64 + tx4];
        float a[8] = {a0.x, a0.y, a0.z, a0.w, a1.x, a1.y, a1.z, a1.w};
        float b[8] = {b0.x, b0.y, b0.z, b0.w, b1.x, b1.y, b1.z, b1.w};
        #pragma unroll
        for (int i = 0; i < 8; i++)
            #pragma unroll
            for (int j = 0; j < 8; j++) acc[i][j] += a[i] * b[j];
    }
}

#define ROW_OF(i)  ((i) < 4 ? (ty4 + (i)) : (64 + ty4 + (i) - 4))

// ---------------------------------------------------------------------------
// Kernel 1: projections. out[o][n] = sum_c W[o][c] x[c][n] + bias
// A = W (transpose-load), B = x (direct). blockIdx.y selects theta/phi/g.
// ---------------------------------------------------------------------------
__global__ __launch_bounds__(256, 2) void k_proj(
    const float* __restrict__ x,
    const float* __restrict__ w_theta, const float* __restrict__ b_theta,
    const float* __restrict__ w_phi,   const float* __restrict__ b_phi,
    const float* __restrict__ w_g,     const float* __restrict__ b_g)
{
    const int b  = blockIdx.z;
    const int nT = blockIdx.x * 128;
    const float* Wp; const float* Bp;
    if (blockIdx.y == 0)      { Wp = w_theta; Bp = b_theta; }
    else if (blockIdx.y == 1) { Wp = w_phi;   Bp = b_phi;   }
    else                      { Wp = w_g;     Bp = b_g;     }
    const int oT = blockIdx.y * 128;

    __shared__ float As[2][8][132], Bs[2][8][132];
    const int tid = threadIdx.x;
    const int tx4 = (tid & 15) * 4, ty4 = (tid >> 4) * 4;
    // transpose-load indices for A (rows=o, k contiguous in source)
    const int alr = tid >> 1, als = (tid & 1) * 4;
    // direct-load indices for B
    const int blk = tid >> 5, blc = (tid & 31) * 4;

    const float* xb = x + (size_t)b * C_IN * NN + nT;
    float acc[8][8] = {};

    float4 ra = *(const float4*)&Wp[(size_t)alr * C_IN + als];
    float4 rb = *(const float4*)&xb[(size_t)blk * NN + blc];
    As[0][als + 0][alr] = ra.x; As[0][als + 1][alr] = ra.y;
    As[0][als + 2][alr] = ra.z; As[0][als + 3][alr] = ra.w;
    *(float4*)&Bs[0][blk][blc] = rb;
    __syncthreads();

    const int nk = C_IN / 8;
    for (int ks = 0; ks < nk; ks++) {
        int cur = ks & 1, nxt = cur ^ 1;
        if (ks + 1 < nk) {
            ra = *(const float4*)&Wp[(size_t)alr * C_IN + (ks + 1) * 8 + als];
            rb = *(const float4*)&xb[(size_t)((ks + 1) * 8 + blk) * NN + blc];
        }
        mma8x8(As[cur], Bs[cur], acc, ty4, tx4);
        if (ks + 1 < nk) {
            As[nxt][als + 0][alr] = ra.x; As[nxt][als + 1][alr] = ra.y;
            As[nxt][als + 2][alr] = ra.z; As[nxt][als + 3][alr] = ra.w;
            *(float4*)&Bs[nxt][blk][blc] = rb;
            __syncthreads();
        }
    }

    #pragma unroll
    for (int i = 0; i < 8; i++) {
        int o = ROW_OF(i);
        float bias = Bp[o];
        float* dst = &d_proj[b][oT + o][nT];
        float4 v0 = {acc[i][0] + bias, acc[i][1] + bias, acc[i][2] + bias, acc[i][3] + bias};
        float4 v1 = {acc[i][4] + bias, acc[i][5] + bias, acc[i][6] + bias, acc[i][7] + bias};
        *(float4*)&dst[tx4] = v0;
        *(float4*)&dst[64 + tx4] = v1;
    }
}

// ---------------------------------------------------------------------------
// Kernel 2: 2x2 maxpool of phi and g (float4, 2 outputs per tensor per thread)
// ---------------------------------------------------------------------------
__global__ void k_pool()
{
    int idx = blockIdx.x * blockDim.x + threadIdx.x;   // BATCH*C_I*512
    if (idx >= BATCH * C_I * 512) return;
    int p  = idx & 15;            // wp pair
    int hp = (idx >> 4) & 31;
    int ci = (idx >> 9) & 127;
    int b  = idx >> 16;
    int n0 = (hp * 2) * WW + p * 4;
    int m  = hp * 32 + p * 2;

    {
        const float* src = &d_proj[b][128 + ci][0];
        float4 r0 = *(const float4*)&src[n0];
        float4 r1 = *(const float4*)&src[n0 + WW];
        float v0 = fmaxf(fmaxf(r0.x, r0.y), fmaxf(r1.x, r1.y));
        float v1 = fmaxf(fmaxf(r0.z, r0.w), fmaxf(r1.z, r1.w));
        *(float2*)&d_phi_p[b][ci][m] = make_float2(v0, v1);
    }
    {
        const float* src = &d_proj[b][256 + ci][0];
        float4 r0 = *(const float4*)&src[n0];
        float4 r1 = *(const float4*)&src[n0 + WW];
        float v0 = fmaxf(fmaxf(r0.x, r0.y), fmaxf(r1.x, r1.y));
        float v1 = fmaxf(fmaxf(r0.z, r0.w), fmaxf(r1.z, r1.w));
        *(float2*)&d_g_p[b][ci][m] = make_float2(v0, v1);
    }
}

// ---------------------------------------------------------------------------
// Kernel 3: scores f[n][m] = sum_k theta[k][n] phi[k][m]. Both direct loads.
// ---------------------------------------------------------------------------
__global__ __launch_bounds__(256, 2) void k_scores()
{
    const int b  = blockIdx.z;
    const int nT = blockIdx.y * 128;
    const int mT = blockIdx.x * 128;

    __shared__ float As[2][8][132], Bs[2][8][132];
    const int tid = threadIdx.x;
    const int tx4 = (tid & 15) * 4, ty4 = (tid >> 4) * 4;
    const int lk = tid >> 5, lc = (tid & 31) * 4;
    float acc[8][8] = {};

    float4 ra = *(const float4*)&d_proj[b][lk][nT + lc];
    float4 rb = *(const float4*)&d_phi_p[b][lk][mT + lc];
    *(float4*)&As[0][lk][lc] = ra;
    *(float4*)&Bs[0][lk][lc] = rb;
    __syncthreads();

    const int nk = C_I / 8;
    for (int ks = 0; ks < nk; ks++) {
        int cur = ks & 1, nxt = cur ^ 1;
        if (ks + 1 < nk) {
            ra = *(const float4*)&d_proj[b][(ks + 1) * 8 + lk][nT + lc];
            rb = *(const float4*)&d_phi_p[b][(ks + 1) * 8 + lk][mT + lc];
        }
        mma8x8(As[cur], Bs[cur], acc, ty4, tx4);
        if (ks + 1 < nk) {
            *(float4*)&As[nxt][lk][lc] = ra;
            *(float4*)&Bs[nxt][lk][lc] = rb;
            __syncthreads();
        }
    }

    #pragma unroll
    for (int i = 0; i < 8; i++) {
        int n = ROW_OF(i);
        float* dst = &d_f[b][nT + n][mT];
        *(float4*)&dst[tx4]      = *(float4*)&acc[i][0];
        *(float4*)&dst[64 + tx4] = *(float4*)&acc[i][4];
    }
}

// ---------------------------------------------------------------------------
// Kernel 4: softmax over M=1024, float4 + warp shuffles, in place.
// ---------------------------------------------------------------------------
__global__ void k_softmax()
{
    const int row = blockIdx.x;
    float4* f = (float4*)(&d_f[0][0][0] + (size_t)row * MM);
    const int t = threadIdx.x;
    const int lane = t & 31, warp = t >> 5;
    __shared__ float red[8];

    float4 v = f[t];
    float mx = fmaxf(fmaxf(v.x, v.y), fmaxf(v.z, v.w));
    #pragma unroll
    for (int o = 16; o > 0; o >>= 1) mx = fmaxf(mx, __shfl_xor_sync(0xffffffffu, mx, o));
    if (lane == 0) red[warp] = mx;
    __syncthreads();
    mx = -1e30f;
    #pragma unroll
    for (int i = 0; i < 8; i++) mx = fmaxf(mx, red[i]);
    __syncthreads();

    v.x = __expf(v.x - mx); v.y = __expf(v.y - mx);
    v.z = __expf(v.z - mx); v.w = __expf(v.w - mx);
    float s = v.x + v.y + v.z + v.w;
    #pragma unroll
    for (int o = 16; o > 0; o >>= 1) s += __shfl_xor_sync(0xffffffffu, s, o);
    if (lane == 0) red[warp] = s;
    __syncthreads();
    s = 0.f;
    #pragma unroll
    for (int i = 0; i < 8; i++) s += red[i];
    float inv = 1.f / s;

    v.x *= inv; v.y *= inv; v.z *= inv; v.w *= inv;
    f[t] = v;
}

// ---------------------------------------------------------------------------
// Kernel 5: y[ci][n] = sum_m g[ci][m] f[n][m]. Both transpose-loads. K=1024.
// ---------------------------------------------------------------------------
__global__ __launch_bounds__(256, 2) void k_y()
{
    const int b  = blockIdx.z;
    const int nT = blockIdx.x * 128;

    __shared__ float As[2][8][132], Bs[2][8][132];
    const int tid = threadIdx.x;
    const int tx4 = (tid & 15) * 4, ty4 = (tid >> 4) * 4;
    const int lr = tid >> 1, ls = (tid & 1) * 4;
    float acc[8][8] = {};

    float4 ra = *(const float4*)&d_g_p[b][lr][ls];
    float4 rb = *(const float4*)&d_f[b][nT + lr][ls];
    As[0][ls + 0][lr] = ra.x; As[0][ls + 1][lr] = ra.y;
    As[0][ls + 2][lr] = ra.z; As[0][ls + 3][lr] = ra.w;
    Bs[0][ls + 0][lr] = rb.x; Bs[0][ls + 1][lr] = rb.y;
    Bs[0][ls + 2][lr] = rb.z; Bs[0][ls + 3][lr] = rb.w;
    __syncthreads();

    const int nk = MM / 8;
    for (int ks = 0; ks < nk; ks++) {
        int cur = ks & 1, nxt = cur ^ 1;
        if (ks + 1 < nk) {
            int m0 = (ks + 1) * 8 + ls;
            ra = *(const float4*)&d_g_p[b][lr][m0];
            rb = *(const float4*)&d_f[b][nT + lr][m0];
        }
        mma8x8(As[cur], Bs[cur], acc, ty4, tx4);
        if (ks + 1 < nk) {
            As[nxt][ls + 0][lr] = ra.x; As[nxt][ls + 1][lr] = ra.y;
            As[nxt][ls + 2][lr] = ra.z; As[nxt][ls + 3][lr] = ra.w;
            Bs[nxt][ls + 0][lr] = rb.x; Bs[nxt][ls + 1][lr] = rb.y;
            Bs[nxt][ls + 2][lr] = rb.z; Bs[nxt][ls + 3][lr] = rb.w;
            __syncthreads();
        }
    }

    #pragma unroll
    for (int i = 0; i < 8; i++) {
        int ci = ROW_OF(i);
        float* dst = &d_y[b][ci][nT];
        *(float4*)&dst[tx4]      = *(float4*)&acc[i][0];
        *(float4*)&dst[64 + tx4] = *(float4*)&acc[i][4];
    }
}

// ---------------------------------------------------------------------------
// Kernel 6: wy[c][n] = b_w[c] + sum_k w_w[c][k] y[k][n]. A transpose, B direct.
// ---------------------------------------------------------------------------
__global__ __launch_bounds__(256, 2) void k_wy(const float* __restrict__ w_w,
                                               const float* __restrict__ b_w)
{
    const int b  = blockIdx.z;
    const int cT = blockIdx.y * 128;
    const int nT = blockIdx.x * 128;

    __shared__ float As[2][8][132], Bs[2][8][132];
    const int tid = threadIdx.x;
    const int tx4 = (tid & 15) * 4, ty4 = (tid >> 4) * 4;
    const int alr = tid >> 1, als = (tid & 1) * 4;
    const int blk = tid >> 5, blc = (tid & 31) * 4;
    float acc[8][8] = {};

    float4 ra = *(const float4*)&w_w[(size_t)(cT + alr) * C_I + als];
    float4 rb = *(const float4*)&d_y[b][blk][nT + blc];
    As[0][als + 0][alr] = ra.x; As[0][als + 1][alr] = ra.y;
    As[0][als + 2][alr] = ra.z; As[0][als + 3][alr] = ra.w;
    *(float4*)&Bs[0][blk][blc] = rb;
    __syncthreads();

    const int nk = C_I / 8;
    for (int ks = 0; ks < nk; ks++) {
        int cur = ks & 1, nxt = cur ^ 1;
        if (ks + 1 < nk) {
            ra = *(const float4*)&w_w[(size_t)(cT + alr) * C_I + (ks + 1) * 8 + als];
            rb = *(const float4*)&d_y[b][(ks + 1) * 8 + blk][nT + blc];
        }
        mma8x8(As[cur], Bs[cur], acc, ty4, tx4);
        if (ks + 1 < nk) {
            As[nxt][als + 0][alr] = ra.x; As[nxt][als + 1][alr] = ra.y;
            As[nxt][als + 2][alr] = ra.z; As[nxt][als + 3][alr] = ra.w;
            *(float4*)&Bs[nxt][blk][blc] = rb;
            __syncthreads();
        }
    }

    #pragma unroll
    for (int i = 0; i < 8; i++) {
        int c = cT + ROW_OF(i);
        float bias = b_w[c];
        float* dst = &d_wy[b][c][nT];
        float4 v0 = {acc[i][0] + bias, acc[i][1] + bias, acc[i][2] + bias, acc[i][3] + bias};
        float4 v1 = {acc[i][4] + bias, acc[i][5] + bias, acc[i][6] + bias, acc[i][7] + bias};
        *(float4*)&dst[tx4] = v0;
        *(float4*)&dst[64 + tx4] = v1;
    }
}

// ---------------------------------------------------------------------------
// Kernel 7: BN stats per channel
// ---------------------------------------------------------------------------
__global__ void k_bnstat(const float* __restrict__ gamma, const float* __restrict__ beta)
{
    const int c = blockIdx.x;
    const int t = threadIdx.x;
    float s = 0.f, ss = 0.f;
    for (int b = 0; b < BATCH; b++) {
        const float4* p = (const float4*)&d_wy[b][c][0];
        for (int i = t; i < NN / 4; i += 256) {
            float4 v = p[i];
            s  += v.x + v.y + v.z + v.w;
            ss += v.x * v.x + v.y * v.y + v.z * v.z + v.w * v.w;
        }
    }
    const int lane = t & 31, warp = t >> 5;
    #pragma unroll
    for (int o = 16; o > 0; o >>= 1) {
        s  += __shfl_xor_sync(0xffffffffu, s, o);
        ss += __shfl_xor_sync(0xffffffffu, ss, o);
    }
    __shared__ float rs[8], rss[8];
    if (lane == 0) { rs[warp] = s; rss[warp] = ss; }
    __syncthreads();
    if (t == 0) {
        float S = 0.f, SS = 0.f;
        #pragma unroll
        for (int i = 0; i < 8; i++) { S += rs[i]; SS += rss[i]; }
        const float invN = 1.f / (BATCH * NN);
        float mean = S * invN;
        float var  = SS * invN - mean * mean;
        float istd = rsqrtf(var + 1e-5f);
        float sc = gamma[c] * istd;
        d_scale[c] = sc;
        d_shift[c] = beta[c] - mean * sc;
    }
}

// ---------------------------------------------------------------------------
// Kernel 8: out = BN(wy) + x  (float4)
// ---------------------------------------------------------------------------
__global__ void k_final(const float* __restrict__ x, float* __restrict__ out)
{
    size_t i4 = (size_t)blockIdx.x * blockDim.x + threadIdx.x;
    if (i4 >= (size_t)BATCH * C_IN * NN / 4) return;
    int c = (int)((i4 >> 10) & (C_IN - 1));
    float sc = d_scale[c], sh = d_shift[c];
    float4 w = ((const float4*)&d_wy[0][0][0])[i4];
    float4 xv = ((const float4*)x)[i4];
    float4 o;
    o.x = w.x * sc + sh + xv.x;
    o.y = w.y * sc + sh + xv.y;
    o.z = w.z * sc + sh + xv.z;
    o.w = w.w * sc + sh + xv.w;
    ((float4*)out)[i4] = o;
}

// ---------------------------------------------------------------------------
extern "C" void kernel_launch(void* const* d_in, const int* in_sizes, int n_in,
                              void* d_out, int out_size)
{
    const float* x       = (const float*)d_in[0];
    const float* w_g     = (const float*)d_in[1];
    const float* b_g     = (const float*)d_in[2];
    const float* w_theta = (const float*)d_in[3];
    const float* b_theta = (const float*)d_in[4];
    const float* w_phi   = (const float*)d_in[5];
    const float* b_phi   = (const float*)d_in[6];
    const float* w_w     = (const float*)d_in[7];
    const float* b_w     = (const float*)d_in[8];
    const float* gamma   = (const float*)d_in[9];
    const float* beta    = (const float*)d_in[10];
    float* out = (float*)d_out;

    k_proj   <<<dim3(NN / 128, 3, BATCH), 256>>>(x, w_theta, b_theta, w_phi, b_phi, w_g, b_g);
    k_pool   <<<(BATCH * C_I * 512 + 255) / 256, 256>>>();
    k_scores <<<dim3(MM / 128, NN / 128, BATCH), 256>>>();
    k_softmax<<<BATCH * NN, 256>>>();
    k_y      <<<dim3(NN / 128, 1, BATCH), 256>>>();
    k_wy     <<<dim3(NN / 128, C_IN / 128, BATCH), 256>>>(w_w, b_w);
    k_bnstat <<<C_IN, 256>>>(gamma, beta);
    k_final  <<<(BATCH * C_IN * NN / 4 + 255) / 256, 256>>>(x, out);
}

// round 3
// speedup vs baseline: 2.0350x; 1.1337x over previous
#include <cuda_runtime.h>
#include <math.h>

#define BATCH 8
#define C_IN 256
#define C_I  128
#define WW   64
#define NN   4096   // H*W
#define MM   1024   // pooled spatial

// Scratch
__device__ float d_theta[BATCH][C_I][NN];
__device__ float d_phi_p[BATCH][C_I][MM];
__device__ float d_g_p[BATCH][C_I][MM];
__device__ float d_f[BATCH][NN][MM];          // holds exp(f), unnormalized
__device__ float d_fpart[BATCH][NN][8];       // per-(row, m-tile) partial sums
__device__ float d_inv[BATCH][NN];            // 1/rowsum
__device__ float d_y[BATCH][C_I][NN];
__device__ float d_wy[BATCH][C_IN][NN];
__device__ float d_bns [BATCH][C_IN][32];     // BN partial sums per n-tile
__device__ float d_bnss[BATCH][C_IN][32];     // BN partial sumsq
__device__ float d_scale[C_IN];
__device__ float d_shift[C_IN];

// ---------------------------------------------------------------------------
// 128x128x8 double-buffered SGEMM core, split 4+4 micro-tile.
// ---------------------------------------------------------------------------
__device__ __forceinline__ void mma8x8(const float (*As)[132], const float (*Bs)[132],
                                       float acc[8][8], int ty4, int tx4)
{
    #pragma unroll
    for (int k = 0; k < 8; k++) {
        float4 a0 = *(const float4*)&As[k][ty4];
        float4 a1 = *(const float4*)&As[k][64 + ty4];
        float4 b0 = *(const float4*)&Bs[k][tx4];
        float4 b1 = *(const float4*)&Bs[k][64 + tx4];
        float a[8] = {a0.x, a0.y, a0.z, a0.w, a1.x, a1.y, a1.z, a1.w};
        float b[8] = {b0.x, b0.y, b0.z, b0.w, b1.x, b1.y, b1.z, b1.w};
        #pragma unroll
        for (int i = 0; i < 8; i++)
            #pragma unroll
            for (int j = 0; j < 8; j++) acc[i][j] += a[i] * b[j];
    }
}

#define ROW_OF(i)  ((i) < 4 ? (ty4 + (i)) : (64 + ty4 + (i) - 4))

// 16-lane (same warp-half) sum reduce, lanes grouped by tx = tid&15
__device__ __forceinline__ float red16(float v)
{
    #pragma unroll
    for (int o = 8; o > 0; o >>= 1) v += __shfl_xor_sync(0xffffffffu, v, o);
    return v;
}

// ---------------------------------------------------------------------------
// Kernel 1: projections with fused 2x2 maxpool for phi/g.
// y==0: theta -> d_theta (unpooled). y==1: phi -> d_phi_p. y==2: g -> d_g_p.
// An n-tile of 128 spans exactly image rows {2*bx, 2*bx+1}.
// ---------------------------------------------------------------------------
__global__ __launch_bounds__(256, 2) void k_proj(
    const float* __restrict__ x,
    const float* __restrict__ w_theta, const float* __restrict__ b_theta,
    const float* __restrict__ w_phi,   const float* __restrict__ b_phi,
    const float* __restrict__ w_g,     const float* __restrict__ b_g)
{
    const int b  = blockIdx.z;
    const int nT = blockIdx.x * 128;
    const float* Wp; const float* Bp;
    if (blockIdx.y == 0)      { Wp = w_theta; Bp = b_theta; }
    else if (blockIdx.y == 1) { Wp = w_phi;   Bp = b_phi;   }
    else                      { Wp = w_g;     Bp = b_g;     }

    __shared__ float As[2][8][132], Bs[2][8][132];
    const int tid = threadIdx.x;
    const int tx4 = (tid & 15) * 4, ty4 = (tid >> 4) * 4;
    const int alr = tid >> 1, als = (tid & 1) * 4;     // A transpose-load
    const int blk = tid >> 5, blc = (tid & 31) * 4;    // B direct-load

    const float* xb = x + (size_t)b * C_IN * NN + nT;
    float acc[8][8] = {};

    float4 ra = *(const float4*)&Wp[(size_t)alr * C_IN + als];
    float4 rb = *(const float4*)&xb[(size_t)blk * NN + blc];
    As[0][als + 0][alr] = ra.x; As[0][als + 1][alr] = ra.y;
    As[0][als + 2][alr] = ra.z; As[0][als + 3][alr] = ra.w;
    *(float4*)&Bs[0][blk][blc] = rb;
    __syncthreads();

    const int nk = C_IN / 8;
    for (int ks = 0; ks < nk; ks++) {
        int cur = ks & 1, nxt = cur ^ 1;
        if (ks + 1 < nk) {
            ra = *(const float4*)&Wp[(size_t)alr * C_IN + (ks + 1) * 8 + als];
            rb = *(const float4*)&xb[(size_t)((ks + 1) * 8 + blk) * NN + blc];
        }
        mma8x8(As[cur], Bs[cur], acc, ty4, tx4);
        if (ks + 1 < nk) {
            As[nxt][als + 0][alr] = ra.x; As[nxt][als + 1][alr] = ra.y;
            As[nxt][als + 2][alr] = ra.z; As[nxt][als + 3][alr] = ra.w;
            *(float4*)&Bs[nxt][blk][blc] = rb;
            __syncthreads();
        }
    }

    if (blockIdx.y == 0) {
        #pragma unroll
        for (int i = 0; i < 8; i++) {
            int o = ROW_OF(i);
            float bias = Bp[o];
            float* dst = &d_theta[b][o][nT];
            float4 v0 = {acc[i][0] + bias, acc[i][1] + bias, acc[i][2] + bias, acc[i][3] + bias};
            float4 v1 = {acc[i][4] + bias, acc[i][5] + bias, acc[i][6] + bias, acc[i][7] + bias};
            *(float4*)&dst[tx4] = v0;
            *(float4*)&dst[64 + tx4] = v1;
        }
    } else {
        // fused 2x2 maxpool: cols j (row h0=w tx4+j) and 4+j (row h0+1, same w)
        float (*dst)[MM] = (blockIdx.y == 1) ? d_phi_p[b] : d_g_p[b];
        const int m0 = blockIdx.x * 32 + (tid & 15) * 2;
        #pragma unroll
        for (int i = 0; i < 8; i++) {
            int o = ROW_OF(i);
            float bias = Bp[o];
            float v0 = fmaxf(fmaxf(acc[i][0], acc[i][1]), fmaxf(acc[i][4], acc[i][5])) + bias;
            float v1 = fmaxf(fmaxf(acc[i][2], acc[i][3]), fmaxf(acc[i][6], acc[i][7])) + bias;
            *(float2*)&dst[o][m0] = make_float2(v0, v1);
        }
    }
}

// ---------------------------------------------------------------------------
// Kernel 2: scores + exp + deterministic partial row sums.
// d_f[n][m] = exp(sum_k theta[k][n] phi[k][m]); d_fpart[n][mtile] = partial sum.
// ---------------------------------------------------------------------------
__global__ __launch_bounds__(256, 2) void k_scores()
{
    const int b  = blockIdx.z;
    const int nT = blockIdx.y * 128;
    const int mT = blockIdx.x * 128;

    __shared__ float As[2][8][132], Bs[2][8][132];
    const int tid = threadIdx.x;
    const int tx4 = (tid & 15) * 4, ty4 = (tid >> 4) * 4;
    const int lk = tid >> 5, lc = (tid & 31) * 4;
    float acc[8][8] = {};

    float4 ra = *(const float4*)&d_theta[b][lk][nT + lc];
    float4 rb = *(const float4*)&d_phi_p[b][lk][mT + lc];
    *(float4*)&As[0][lk][lc] = ra;
    *(float4*)&Bs[0][lk][lc] = rb;
    __syncthreads();

    const int nk = C_I / 8;
    for (int ks = 0; ks < nk; ks++) {
        int cur = ks & 1, nxt = cur ^ 1;
        if (ks + 1 < nk) {
            ra = *(const float4*)&d_theta[b][(ks + 1) * 8 + lk][nT + lc];
            rb = *(const float4*)&d_phi_p[b][(ks + 1) * 8 + lk][mT + lc];
        }
        mma8x8(As[cur], Bs[cur], acc, ty4, tx4);
        if (ks + 1 < nk) {
            *(float4*)&As[nxt][lk][lc] = ra;
            *(float4*)&Bs[nxt][lk][lc] = rb;
            __syncthreads();
        }
    }

    const int tx = tid & 15;
    #pragma unroll
    for (int i = 0; i < 8; i++) {
        int n = ROW_OF(i);
        float psum = 0.f;
        #pragma unroll
        for (int j = 0; j < 8; j++) { acc[i][j] = __expf(acc[i][j]); psum += acc[i][j]; }
        float* dst = &d_f[b][nT + n][mT];
        *(float4*)&dst[tx4]      = *(float4*)&acc[i][0];
        *(float4*)&dst[64 + tx4] = *(float4*)&acc[i][4];
        psum = red16(psum);
        if (tx == 0) d_fpart[b][nT + n][blockIdx.x] = psum;
    }
}

// ---------------------------------------------------------------------------
// Kernel 3: finalize row sums -> 1/sum
// ---------------------------------------------------------------------------
__global__ void k_rowfin()
{
    int r = blockIdx.x * 256 + threadIdx.x;   // 0..32767
    int b = r >> 12, n = r & (NN - 1);
    const float* p = d_fpart[b][n];
    float s = 0.f;
    #pragma unroll
    for (int i = 0; i < 8; i++) s += p[i];
    d_inv[b][n] = 1.f / s;
}

// ---------------------------------------------------------------------------
// Kernel 4: y[ci][n] = inv[n] * sum_m g[ci][m] expf[n][m].  K=1024.
// ---------------------------------------------------------------------------
__global__ __launch_bounds__(256, 2) void k_y()
{
    const int b  = blockIdx.z;
    const int nT = blockIdx.x * 128;

    __shared__ float As[2][8][132], Bs[2][8][132];
    const int tid = threadIdx.x;
    const int tx4 = (tid & 15) * 4, ty4 = (tid >> 4) * 4;
    const int lr = tid >> 1, ls = (tid & 1) * 4;
    float acc[8][8] = {};

    float4 ra = *(const float4*)&d_g_p[b][lr][ls];
    float4 rb = *(const float4*)&d_f[b][nT + lr][ls];
    As[0][ls + 0][lr] = ra.x; As[0][ls + 1][lr] = ra.y;
    As[0][ls + 2][lr] = ra.z; As[0][ls + 3][lr] = ra.w;
    Bs[0][ls + 0][lr] = rb.x; Bs[0][ls + 1][lr] = rb.y;
    Bs[0][ls + 2][lr] = rb.z; Bs[0][ls + 3][lr] = rb.w;
    __syncthreads();

    const int nk = MM / 8;
    for (int ks = 0; ks < nk; ks++) {
        int cur = ks & 1, nxt = cur ^ 1;
        if (ks + 1 < nk) {
            int m0 = (ks + 1) * 8 + ls;
            ra = *(const float4*)&d_g_p[b][lr][m0];
            rb = *(const float4*)&d_f[b][nT + lr][m0];
        }
        mma8x8(As[cur], Bs[cur], acc, ty4, tx4);
        if (ks + 1 < nk) {
            As[nxt][ls + 0][lr] = ra.x; As[nxt][ls + 1][lr] = ra.y;
            As[nxt][ls + 2][lr] = ra.z; As[nxt][ls + 3][lr] = ra.w;
            Bs[nxt][ls + 0][lr] = rb.x; Bs[nxt][ls + 1][lr] = rb.y;
            Bs[nxt][ls + 2][lr] = rb.z; Bs[nxt][ls + 3][lr] = rb.w;
            __syncthreads();
        }
    }

    float4 inv0 = *(const float4*)&d_inv[b][nT + tx4];
    float4 inv1 = *(const float4*)&d_inv[b][nT + 64 + tx4];
    #pragma unroll
    for (int i = 0; i < 8; i++) {
        int ci = ROW_OF(i);
        float* dst = &d_y[b][ci][nT];
        float4 v0 = {acc[i][0] * inv0.x, acc[i][1] * inv0.y, acc[i][2] * inv0.z, acc[i][3] * inv0.w};
        float4 v1 = {acc[i][4] * inv1.x, acc[i][5] * inv1.y, acc[i][6] * inv1.z, acc[i][7] * inv1.w};
        *(float4*)&dst[tx4] = v0;
        *(float4*)&dst[64 + tx4] = v1;
    }
}

// ---------------------------------------------------------------------------
// Kernel 5: wy[c][n] = b_w[c] + sum_k w_w[c][k] y[k][n]; fused BN partials.
// ---------------------------------------------------------------------------
__global__ __launch_bounds__(256, 2) void k_wy(const float* __restrict__ w_w,
                                               const float* __restrict__ b_w)
{
    const int b  = blockIdx.z;
    const int cT = blockIdx.y * 128;
    const int nT = blockIdx.x * 128;

    __shared__ float As[2][8][132], Bs[2][8][132];
    const int tid = threadIdx.x;
    const int tx4 = (tid & 15) * 4, ty4 = (tid >> 4) * 4;
    const int alr = tid >> 1, als = (tid & 1) * 4;
    const int blk = tid >> 5, blc = (tid & 31) * 4;
    float acc[8][8] = {};

    float4 ra = *(const float4*)&w_w[(size_t)(cT + alr) * C_I + als];
    float4 rb = *(const float4*)&d_y[b][blk][nT + blc];
    As[0][als + 0][alr] = ra.x; As[0][als + 1][alr] = ra.y;
    As[0][als + 2][alr] = ra.z; As[0][als + 3][alr] = ra.w;
    *(float4*)&Bs[0][blk][blc] = rb;
    __syncthreads();

    const int nk = C_I / 8;
    for (int ks = 0; ks < nk; ks++) {
        int cur = ks & 1, nxt = cur ^ 1;
        if (ks + 1 < nk) {
            ra = *(const float4*)&w_w[(size_t)(cT + alr) * C_I + (ks + 1) * 8 + als];
            rb = *(const float4*)&d_y[b][(ks + 1) * 8 + blk][nT + blc];
        }
        mma8x8(As[cur], Bs[cur], acc, ty4, tx4);
        if (ks + 1 < nk) {
            As[nxt][als + 0][alr] = ra.x; As[nxt][als + 1][alr] = ra.y;
            As[nxt][als + 2][alr] = ra.z; As[nxt][als + 3][alr] = ra.w;
            *(float4*)&Bs[nxt][blk][blc] = rb;
            __syncthreads();
        }
    }

    const int tx = tid & 15;
    #pragma unroll
    for (int i = 0; i < 8; i++) {
        int c = cT + ROW_OF(i);
        float bias = b_w[c];
        float s = 0.f, ss = 0.f;
        #pragma unroll
        for (int j = 0; j < 8; j++) {
            acc[i][j] += bias;
            s  += acc[i][j];
            ss += acc[i][j] * acc[i][j];
        }
        float* dst = &d_wy[b][c][nT];
        *(float4*)&dst[tx4]      = *(float4*)&acc[i][0];
        *(float4*)&dst[64 + tx4] = *(float4*)&acc[i][4];
        s  = red16(s);
        ss = red16(ss);
        if (tx == 0) { d_bns[b][c][blockIdx.x] = s; d_bnss[b][c][blockIdx.x] = ss; }
    }
}

// ---------------------------------------------------------------------------
// Kernel 6: BN finalize (256 partials per channel = 8 batch x 32 tiles)
// ---------------------------------------------------------------------------
__global__ void k_bnfin(const float* __restrict__ gamma, const float* __restrict__ beta)
{
    const int c = blockIdx.x;
    const int t = threadIdx.x;
    const int b = t >> 5, tile = t & 31;
    float s  = d_bns [b][c][tile];
    float ss = d_bnss[b][c][tile];
    const int lane = t & 31, warp = t >> 5;
    #pragma unroll
    for (int o = 16; o > 0; o >>= 1) {
        s  += __shfl_xor_sync(0xffffffffu, s, o);
        ss += __shfl_xor_sync(0xffffffffu, ss, o);
    }
    __shared__ float rs[8], rss[8];
    if (lane == 0) { rs[warp] = s; rss[warp] = ss; }
    __syncthreads();
    if (t == 0) {
        float S = 0.f, SS = 0.f;
        #pragma unroll
        for (int i = 0; i < 8; i++) { S += rs[i]; SS += rss[i]; }
        const float invN = 1.f / (BATCH * NN);
        float mean = S * invN;
        float var  = SS * invN - mean * mean;
        float istd = rsqrtf(var + 1e-5f);
        float sc = gamma[c] * istd;
        d_scale[c] = sc;
        d_shift[c] = beta[c] - mean * sc;
    }
}

// ---------------------------------------------------------------------------
// Kernel 7: out = BN(wy) + x
// ---------------------------------------------------------------------------
__global__ void k_final(const float* __restrict__ x, float* __restrict__ out)
{
    size_t i4 = (size_t)blockIdx.x * blockDim.x + threadIdx.x;
    if (i4 >= (size_t)BATCH * C_IN * NN / 4) return;
    int c = (int)((i4 >> 10) & (C_IN - 1));
    float sc = d_scale[c], sh = d_shift[c];
    float4 w = ((const float4*)&d_wy[0][0][0])[i4];
    float4 xv = ((const float4*)x)[i4];
    float4 o;
    o.x = w.x * sc + sh + xv.x;
    o.y = w.y * sc + sh + xv.y;
    o.z = w.z * sc + sh + xv.z;
    o.w = w.w * sc + sh + xv.w;
    ((float4*)out)[i4] = o;
}

// ---------------------------------------------------------------------------
extern "C" void kernel_launch(void* const* d_in, const int* in_sizes, int n_in,
                              void* d_out, int out_size)
{
    const float* x       = (const float*)d_in[0];
    const float* w_g     = (const float*)d_in[1];
    const float* b_g     = (const float*)d_in[2];
    const float* w_theta = (const float*)d_in[3];
    const float* b_theta = (const float*)d_in[4];
    const float* w_phi   = (const float*)d_in[5];
    const float* b_phi   = (const float*)d_in[6];
    const float* w_w     = (const float*)d_in[7];
    const float* b_w     = (const float*)d_in[8];
    const float* gamma   = (const float*)d_in[9];
    const float* beta    = (const float*)d_in[10];
    float* out = (float*)d_out;

    k_proj  <<<dim3(NN / 128, 3, BATCH), 256>>>(x, w_theta, b_theta, w_phi, b_phi, w_g, b_g);
    k_scores<<<dim3(MM / 128, NN / 128, BATCH), 256>>>();
    k_rowfin<<<BATCH * NN / 256, 256>>>();
    k_y     <<<dim3(NN / 128, 1, BATCH), 256>>>();
    k_wy    <<<dim3(NN / 128, C_IN / 128, BATCH), 256>>>(w_w, b_w);
    k_bnfin <<<C_IN, 256>>>(gamma, beta);
    k_final <<<(BATCH * C_IN * NN / 4 + 255) / 256, 256>>>(x, out);
}

// round 5
// speedup vs baseline: 2.7898x; 1.3709x over previous
#include <cuda_runtime.h>
#include <cuda_bf16.h>
#include <math.h>
#include <stdint.h>

#define BATCH 8
#define C_IN 256
#define C_I  128
#define NN   4096
#define MM   1024

// ---------------------------------------------------------------------------
// Scratch
// ---------------------------------------------------------------------------
__device__ float d_xT [BATCH][NN][C_IN];    // x transposed: [n][c]
__device__ float d_thT[BATCH][NN][C_I];     // theta: [n][ci]
__device__ float d_phi[BATCH][MM][C_I];     // phi pooled: [m][ci]
__device__ float d_g  [BATCH][C_I][MM];     // g pooled: [ci][m]
__device__ float d_f  [BATCH][NN][MM];      // exp(scores), unnormalized
__device__ float d_fpart[BATCH][NN][32];    // per-(row, 32-col subtile) partials
__device__ float d_inv[BATCH][NN];
__device__ float d_yT [BATCH][NN][C_I];     // y: [n][ci]
__device__ float d_wy [BATCH][C_IN][NN];
__device__ float d_bns [BATCH][C_IN][128];
__device__ float d_bnss[BATCH][C_IN][128];
__device__ float d_scale[C_IN];
__device__ float d_shift[C_IN];

// ---------------------------------------------------------------------------
// helpers
// ---------------------------------------------------------------------------
__device__ __forceinline__ uint32_t smem_u32(const void* p) {
    uint32_t a;
    asm("{ .reg .u64 t; cvta.to.shared.u64 t, %1; cvt.u32.u64 %0, t; }" : "=r"(a) : "l"(p));
    return a;
}

#define LDSM_X4(r0, r1, r2, r3, addr) \
    asm volatile("ldmatrix.sync.aligned.m8n8.x4.shared.b16 {%0,%1,%2,%3}, [%4];" \
        : "=r"(r0), "=r"(r1), "=r"(r2), "=r"(r3) : "r"(addr))

#define MMA_BF16(c, a, b) \
    asm volatile("mma.sync.aligned.m16n8k16.row.col.f32.bf16.bf16.f32 " \
        "{%0,%1,%2,%3}, {%4,%5,%6,%7}, {%8,%9}, {%0,%1,%2,%3};" \
        : "+f"((c)[0]), "+f"((c)[1]), "+f"((c)[2]), "+f"((c)[3]) \
        : "r"((a)[0]), "r"((a)[1]), "r"((a)[2]), "r"((a)[3]), "r"((b)[0]), "r"((b)[1]))

// operand tile: 128 rows x 32 bf16 cols, row stride 80 bytes (conflict-free ldmatrix)
#define T_STRIDE 80
#define T_BYTES  (128 * T_STRIDE)            // 10240
#define STAGE_BYTES (4 * T_BYTES)            // Ah, Al, Bh, Bl
#define DSM_BYTES (2 * STAGE_BYTES + 256)    // 82176
#define STG_LD 132                           // fp32 staging stride (floats)

__device__ __forceinline__ void gprefetch(float4* p, const float* __restrict__ src,
                                          int ld, int tid)
{
    #pragma unroll
    for (int i = 0; i < 4; i++) {
        int s = tid + i * 256;
        int r = s >> 3, q = s & 7;
        p[i] = *(const float4*)(src + (size_t)r * ld + q * 4);
    }
}

__device__ __forceinline__ void gstore_split(uint32_t hi, uint32_t lo,
                                             const float4* p, int tid)
{
    #pragma unroll
    for (int i = 0; i < 4; i++) {
        int s = tid + i * 256;
        int r = s >> 3, q = s & 7;
        float4 v = p[i];
        __nv_bfloat16 h0 = __float2bfloat16(v.x);
        __nv_bfloat16 h1 = __float2bfloat16(v.y);
        __nv_bfloat16 h2 = __float2bfloat16(v.z);
        __nv_bfloat16 h3 = __float2bfloat16(v.w);
        __nv_bfloat16 l0 = __float2bfloat16(v.x - __bfloat162float(h0));
        __nv_bfloat16 l1 = __float2bfloat16(v.y - __bfloat162float(h1));
        __nv_bfloat16 l2 = __float2bfloat16(v.z - __bfloat162float(h2));
        __nv_bfloat16 l3 = __float2bfloat16(v.w - __bfloat162float(h3));
        uint32_t hA = ((uint32_t)__bfloat16_as_ushort(h1) << 16) | __bfloat16_as_ushort(h0);
        uint32_t hB = ((uint32_t)__bfloat16_as_ushort(h3) << 16) | __bfloat16_as_ushort(h2);
        uint32_t lA = ((uint32_t)__bfloat16_as_ushort(l1) << 16) | __bfloat16_as_ushort(l0);
        uint32_t lB = ((uint32_t)__bfloat16_as_ushort(l3) << 16) | __bfloat16_as_ushort(l2);
        uint32_t off = (uint32_t)(r * T_STRIDE + q * 8);
        asm volatile("st.shared.v2.b32 [%0], {%1, %2};" :: "r"(hi + off), "r"(hA), "r"(hB));
        asm volatile("st.shared.v2.b32 [%0], {%1, %2};" :: "r"(lo + off), "r"(lA), "r"(lB));
    }
}

// ---------------------------------------------------------------------------
// Mainloop: C[128 x 128] = A[128 x K] * B[128 x K]^T, bf16 split-2 (3 mma terms).
// acc[mf][nf][c]: warp (2x4 grid) owns 64x32; frag rows g,g+8; cols 2t,2t+1.
// ---------------------------------------------------------------------------
__device__ __forceinline__ void gemm_main(const float* __restrict__ A, int ldA,
                                          const float* __restrict__ B, int ldB,
                                          int nk, float acc[4][4][4], uint32_t base)
{
    const int tid = threadIdx.x;
    const int lane = tid & 31, wid = tid >> 5;
    const int warp_m = wid >> 2, warp_n = wid & 3;

    #define TILE(s, a) (base + (uint32_t)((s) * STAGE_BYTES + (a) * T_BYTES))

    {
        float4 p0[4], p1[4];
        gprefetch(p0, A, ldA, tid);
        gprefetch(p1, B, ldB, tid);
        gstore_split(TILE(0, 0), TILE(0, 1), p0, tid);
        gstore_split(TILE(0, 2), TILE(0, 3), p1, tid);
    }
    __syncthreads();

    const int arow = warp_m * 64 + (lane & 15);
    const int brow = warp_n * 32 + (lane & 7) + ((lane >> 4) << 3);
    const uint32_t acol0 = (uint32_t)((lane >> 4) << 4);        // 0 or 16 bytes
    const uint32_t bcol0 = (uint32_t)(((lane >> 3) & 1) << 4);  // 0 or 16 bytes

    for (int ks = 0; ks < nk; ks++) {
        const int s = ks & 1;
        const bool more = (ks + 1 < nk);
        float4 pa[4], pb[4];
        if (more) {
            gprefetch(pa, A + (ks + 1) * 32, ldA, tid);
            gprefetch(pb, B + (ks + 1) * 32, ldB, tid);
        }
        const uint32_t tAh = TILE(s, 0), tAl = TILE(s, 1);
        const uint32_t tBh = TILE(s, 2), tBl = TILE(s, 3);

        #pragma unroll
        for (int kk = 0; kk < 2; kk++) {
            uint32_t ah[4][4], al[4][4], bh[4][2], bl[4][2];
            const uint32_t ka = (uint32_t)(kk * 32) + acol0;
            const uint32_t kb = (uint32_t)(kk * 32) + bcol0;
            #pragma unroll
            for (int mf = 0; mf < 4; mf++) {
                uint32_t ad = (uint32_t)(arow + mf * 16) * T_STRIDE + ka;
                LDSM_X4(ah[mf][0], ah[mf][1], ah[mf][2], ah[mf][3], tAh + ad);
                LDSM_X4(al[mf][0], al[mf][1], al[mf][2], al[mf][3], tAl + ad);
            }
            #pragma unroll
            for (int nf2 = 0; nf2 < 2; nf2++) {
                uint32_t bd = (uint32_t)(brow + nf2 * 16) * T_STRIDE + kb;
                uint32_t r0, r1, r2, r3;
                LDSM_X4(r0, r1, r2, r3, tBh + bd);
                bh[nf2 * 2][0] = r0; bh[nf2 * 2][1] = r1;
                bh[nf2 * 2 + 1][0] = r2; bh[nf2 * 2 + 1][1] = r3;
                LDSM_X4(r0, r1, r2, r3, tBl + bd);
                bl[nf2 * 2][0] = r0; bl[nf2 * 2][1] = r1;
                bl[nf2 * 2 + 1][0] = r2; bl[nf2 * 2 + 1][1] = r3;
            }
            #pragma unroll
            for (int mf = 0; mf < 4; mf++)
                #pragma unroll
                for (int nf = 0; nf < 4; nf++) {
                    MMA_BF16(acc[mf][nf], ah[mf], bh[nf]);
                    MMA_BF16(acc[mf][nf], ah[mf], bl[nf]);
                    MMA_BF16(acc[mf][nf], al[mf], bh[nf]);
                }
        }

        if (more) {
            gstore_split(TILE(s ^ 1, 0), TILE(s ^ 1, 1), pa, tid);
            gstore_split(TILE(s ^ 1, 2), TILE(s ^ 1, 3), pb, tid);
        }
        __syncthreads();
    }
    #undef TILE
}

// fragment geometry
#define FRAG_SETUP() \
    const int lane = threadIdx.x & 31, wid = threadIdx.x >> 5; \
    const int warp_m = wid >> 2, warp_n = wid & 3; \
    const int g = lane >> 2, t2 = (lane & 3) * 2; \
    (void)warp_m; (void)warp_n; (void)g; (void)t2
#define FROW(mf, h) (warp_m * 64 + (mf) * 16 + g + (h) * 8)
#define FCOL(nf)    (warp_n * 32 + (nf) * 8 + t2)

// ---------------------------------------------------------------------------
// Transpose x[b][c][n] -> xT[b][n][c]
// ---------------------------------------------------------------------------
__global__ void k_xt(const float* __restrict__ x)
{
    __shared__ float t[32][33];
    const int b = blockIdx.z, c0 = blockIdx.y * 32, n0 = blockIdx.x * 32;
    const int tx = threadIdx.x, ty = threadIdx.y;
    const float* src = x + ((size_t)b * C_IN + c0) * NN + n0;
    #pragma unroll
    for (int i = 0; i < 32; i += 8) t[ty + i][tx] = src[(size_t)(ty + i) * NN + tx];
    __syncthreads();
    #pragma unroll
    for (int i = 0; i < 32; i += 8) d_xT[b][n0 + ty + i][c0 + tx] = t[tx][ty + i];
}

// ---------------------------------------------------------------------------
// Projections: C[n][o] = xT[n][:]·W[o][:].  y=0 theta, y=1 phi(pool), y=2 g(pool)
// ---------------------------------------------------------------------------
__global__ __launch_bounds__(256) void k_proj(
    const float* __restrict__ w_theta, const float* __restrict__ b_theta,
    const float* __restrict__ w_phi,   const float* __restrict__ b_phi,
    const float* __restrict__ w_g,     const float* __restrict__ b_g)
{
    extern __shared__ char dsm[];
    const uint32_t base = (smem_u32(dsm) + 127u) & ~127u;
    const int b  = blockIdx.z;
    const int nT = blockIdx.x * 128;
    const float* Wp; const float* Bp;
    if (blockIdx.y == 0)      { Wp = w_theta; Bp = b_theta; }
    else if (blockIdx.y == 1) { Wp = w_phi;   Bp = b_phi;   }
    else                      { Wp = w_g;     Bp = b_g;     }

    float acc[4][4][4] = {};
    gemm_main(&d_xT[b][nT][0], C_IN, Wp, C_IN, C_IN / 32, acc, base);

    FRAG_SETUP();
    if (blockIdx.y == 0) {
        // theta: direct write d_thT[n][o] with bias(o)
        #pragma unroll
        for (int mf = 0; mf < 4; mf++)
            #pragma unroll
            for (int nf = 0; nf < 4; nf++) {
                int col = FCOL(nf);
                float2 bias = *(const float2*)&Bp[col];
                *(float2*)&d_thT[b][nT + FROW(mf, 0)][col] =
                    make_float2(acc[mf][nf][0] + bias.x, acc[mf][nf][1] + bias.y);
                *(float2*)&d_thT[b][nT + FROW(mf, 1)][col] =
                    make_float2(acc[mf][nf][2] + bias.x, acc[mf][nf][3] + bias.y);
            }
    } else {
        // stage transposed: stg[o][n]
        float* stg = (float*)dsm;
        #pragma unroll
        for (int mf = 0; mf < 4; mf++)
            #pragma unroll
            for (int nf = 0; nf < 4; nf++) {
                int col = FCOL(nf);
                int r0 = FROW(mf, 0), r1 = FROW(mf, 1);
                stg[col * STG_LD + r0]       = acc[mf][nf][0];
                stg[(col + 1) * STG_LD + r0] = acc[mf][nf][1];
                stg[col * STG_LD + r1]       = acc[mf][nf][2];
                stg[(col + 1) * STG_LD + r1] = acc[mf][nf][3];
            }
        __syncthreads();
        const int m0 = blockIdx.x * 32;
        const int t = threadIdx.x;
        if (blockIdx.y == 1) {
            // phi: d_phi[m][o], coalesced in o
            const int o = t & 31;
            #pragma unroll
            for (int i = 0; i < 4; i++) {
                int wp = (t >> 5) + i * 8;
                float2 a = *(const float2*)&stg[o * STG_LD + 2 * wp];
                float2 c = *(const float2*)&stg[o * STG_LD + 64 + 2 * wp];
                d_phi[b][m0 + wp][o] = fmaxf(fmaxf(a.x, a.y), fmaxf(c.x, c.y)) + Bp[o];
            }
            #pragma unroll
            for (int i = 0; i < 4; i++) {
                int o2 = 32 + (t & 31) + ((t >> 5) & 3) * 32;  // wait: cover o 32..127
            }
            // remaining o handled below (o blocks of 32 across 128):
            #pragma unroll
            for (int ob = 1; ob < 4; ob++) {
                int oo = ob * 32 + (t & 31);
                #pragma unroll
                for (int i = 0; i < 4; i++) {
                    int wp = (t >> 5) + i * 8;
                    float2 a = *(const float2*)&stg[oo * STG_LD + 2 * wp];
                    float2 c = *(const float2*)&stg[oo * STG_LD + 64 + 2 * wp];
                    d_phi[b][m0 + wp][oo] = fmaxf(fmaxf(a.x, a.y), fmaxf(c.x, c.y)) + Bp[oo];
                }
            }
        } else {
            // g: d_g[o][m], coalesced in m
            const int wp = t & 31;
            #pragma unroll
            for (int i = 0; i < 16; i++) {
                int o = (t >> 5) + i * 8;
                float2 a = *(const float2*)&stg[o * STG_LD + 2 * wp];
                float2 c = *(const float2*)&stg[o * STG_LD + 64 + 2 * wp];
                d_g[b][o][m0 + wp] = fmaxf(fmaxf(a.x, a.y), fmaxf(c.x, c.y)) + Bp[o];
            }
        }
    }
}

// ---------------------------------------------------------------------------
// Scores: C[n][m] = theta[n][:]·phi[m][:]; exp + per-subtile row partials
// ---------------------------------------------------------------------------
__global__ __launch_bounds__(256) void k_scores()
{
    extern __shared__ char dsm[];
    const uint32_t base = (smem_u32(dsm) + 127u) & ~127u;
    const int b  = blockIdx.z;
    const int nT = blockIdx.y * 128;
    const int mT = blockIdx.x * 128;

    float acc[4][4][4] = {};
    gemm_main(&d_thT[b][nT][0], C_I, &d_phi[b][mT][0], C_I, C_I / 32, acc, base);

    FRAG_SETUP();
    float ps[4][2] = {};
    #pragma unroll
    for (int mf = 0; mf < 4; mf++)
        #pragma unroll
        for (int nf = 0; nf < 4; nf++) {
            float e0 = __expf(acc[mf][nf][0]);
            float e1 = __expf(acc[mf][nf][1]);
            float e2 = __expf(acc[mf][nf][2]);
            float e3 = __expf(acc[mf][nf][3]);
            int col = mT + FCOL(nf);
            *(float2*)&d_f[b][nT + FROW(mf, 0)][col] = make_float2(e0, e1);
            *(float2*)&d_f[b][nT + FROW(mf, 1)][col] = make_float2(e2, e3);
            ps[mf][0] += e0 + e1;
            ps[mf][1] += e2 + e3;
        }
    const int sub = blockIdx.x * 4 + warp_n;
    #pragma unroll
    for (int mf = 0; mf < 4; mf++)
        #pragma unroll
        for (int h = 0; h < 2; h++) {
            float v = ps[mf][h];
            v += __shfl_xor_sync(0xffffffffu, v, 1);
            v += __shfl_xor_sync(0xffffffffu, v, 2);
            if ((lane & 3) == 0) d_fpart[b][nT + FROW(mf, h)][sub] = v;
        }
}

// ---------------------------------------------------------------------------
// Row sums -> reciprocal
// ---------------------------------------------------------------------------
__global__ void k_rowfin()
{
    int r = blockIdx.x * 256 + threadIdx.x;
    int b = r >> 12, n = r & (NN - 1);
    const float4* p = (const float4*)&d_fpart[b][n][0];
    float s = 0.f;
    #pragma unroll
    for (int i = 0; i < 8; i++) { float4 v = p[i]; s += v.x + v.y + v.z + v.w; }
    d_inv[b][n] = 1.f / s;
}

// ---------------------------------------------------------------------------
// y: C[n][ci] = f[n][:]·g[ci][:], scaled by inv[n]
// ---------------------------------------------------------------------------
__global__ __launch_bounds__(256) void k_y()
{
    extern __shared__ char dsm[];
    const uint32_t base = (smem_u32(dsm) + 127u) & ~127u;
    const int b  = blockIdx.z;
    const int nT = blockIdx.x * 128;

    float acc[4][4][4] = {};
    gemm_main(&d_f[b][nT][0], MM, &d_g[b][0][0], MM, MM / 32, acc, base);

    FRAG_SETUP();
    #pragma unroll
    for (int mf = 0; mf < 4; mf++)
        #pragma unroll
        for (int h = 0; h < 2; h++) {
            int row = FROW(mf, h);
            float iv = d_inv[b][nT + row];
            #pragma unroll
            for (int nf = 0; nf < 4; nf++) {
                float c0 = acc[mf][nf][2 * h]     * iv;
                float c1 = acc[mf][nf][2 * h + 1] * iv;
                *(float2*)&d_yT[b][nT + row][FCOL(nf)] = make_float2(c0, c1);
            }
        }
}

// ---------------------------------------------------------------------------
// wy: C[c][n] = w_w[c][:]·y[n][:] + bias; fused BN partials
// ---------------------------------------------------------------------------
__global__ __launch_bounds__(256) void k_wy(const float* __restrict__ w_w,
                                            const float* __restrict__ b_w)
{
    extern __shared__ char dsm[];
    const uint32_t base = (smem_u32(dsm) + 127u) & ~127u;
    const int b  = blockIdx.z;
    const int cT = blockIdx.y * 128;
    const int nT = blockIdx.x * 128;

    float acc[4][4][4] = {};
    gemm_main(w_w + (size_t)cT * C_I, C_I, &d_yT[b][nT][0], C_I, C_I / 32, acc, base);

    FRAG_SETUP();
    const int sub = blockIdx.x * 4 + warp_n;
    #pragma unroll
    for (int mf = 0; mf < 4; mf++)
        #pragma unroll
        for (int h = 0; h < 2; h++) {
            int row = FROW(mf, h);
            int c = cT + row;
            float bias = b_w[c];
            float s = 0.f, ss = 0.f;
            #pragma unroll
            for (int nf = 0; nf < 4; nf++) {
                float c0 = acc[mf][nf][2 * h]     + bias;
                float c1 = acc[mf][nf][2 * h + 1] + bias;
                s += c0 + c1;
                ss += c0 * c0 + c1 * c1;
                *(float2*)&d_wy[b][c][nT + FCOL(nf)] = make_float2(c0, c1);
            }
            s  += __shfl_xor_sync(0xffffffffu, s, 1);
            s  += __shfl_xor_sync(0xffffffffu, s, 2);
            ss += __shfl_xor_sync(0xffffffffu, ss, 1);
            ss += __shfl_xor_sync(0xffffffffu, ss, 2);
            if ((lane & 3) == 0) { d_bns[b][c][sub] = s; d_bnss[b][c][sub] = ss; }
        }
}

// ---------------------------------------------------------------------------
// BN finalize: 8 batches x 128 subtiles = 1024 partials per channel
// ---------------------------------------------------------------------------
__global__ void k_bnfin(const float* __restrict__ gamma, const float* __restrict__ beta)
{
    const int c = blockIdx.x;
    const int t = threadIdx.x;
    float s = 0.f, ss = 0.f;
    #pragma unroll
    for (int i = 0; i < 4; i++) {
        int id = t + i * 256;
        int b = id >> 7, tile = id & 127;
        s  += d_bns [b][c][tile];
        ss += d_bnss[b][c][tile];
    }
    const int lane = t & 31, warp = t >> 5;
    #pragma unroll
    for (int o = 16; o > 0; o >>= 1) {
        s  += __shfl_xor_sync(0xffffffffu, s, o);
        ss += __shfl_xor_sync(0xffffffffu, ss, o);
    }
    __shared__ float rs[8], rss[8];
    if (lane == 0) { rs[warp] = s; rss[warp] = ss; }
    __syncthreads();
    if (t == 0) {
        float S = 0.f, SS = 0.f;
        #pragma unroll
        for (int i = 0; i < 8; i++) { S += rs[i]; SS += rss[i]; }
        const float invN = 1.f / (BATCH * NN);
        float mean = S * invN;
        float var  = SS * invN - mean * mean;
        float istd = rsqrtf(var + 1e-5f);
        float sc = gamma[c] * istd;
        d_scale[c] = sc;
        d_shift[c] = beta[c] - mean * sc;
    }
}

// ---------------------------------------------------------------------------
// out = BN(wy) + x
// ---------------------------------------------------------------------------
__global__ void k_final(const float* __restrict__ x, float* __restrict__ out)
{
    size_t i4 = (size_t)blockIdx.x * blockDim.x + threadIdx.x;
    if (i4 >= (size_t)BATCH * C_IN * NN / 4) return;
    int c = (int)((i4 >> 10) & (C_IN - 1));
    float sc = d_scale[c], sh = d_shift[c];
    float4 w  = ((const float4*)&d_wy[0][0][0])[i4];
    float4 xv = ((const float4*)x)[i4];
    float4 o;
    o.x = w.x * sc + sh + xv.x;
    o.y = w.y * sc + sh + xv.y;
    o.z = w.z * sc + sh + xv.z;
    o.w = w.w * sc + sh + xv.w;
    ((float4*)out)[i4] = o;
}

// ---------------------------------------------------------------------------
extern "C" void kernel_launch(void* const* d_in, const int* in_sizes, int n_in,
                              void* d_out, int out_size)
{
    const float* x       = (const float*)d_in[0];
    const float* w_g     = (const float*)d_in[1];
    const float* b_g     = (const float*)d_in[2];
    const float* w_theta = (const float*)d_in[3];
    const float* b_theta = (const float*)d_in[4];
    const float* w_phi   = (const float*)d_in[5];
    const float* b_phi   = (const float*)d_in[6];
    const float* w_w     = (const float*)d_in[7];
    const float* b_w     = (const float*)d_in[8];
    const float* gamma   = (const float*)d_in[9];
    const float* beta    = (const float*)d_in[10];
    float* out = (float*)d_out;

    static int attr_done = 0;
    if (!attr_done) {
        cudaFuncSetAttribute(k_proj,   cudaFuncAttributeMaxDynamicSharedMemorySize, DSM_BYTES);
        cudaFuncSetAttribute(k_scores, cudaFuncAttributeMaxDynamicSharedMemorySize, DSM_BYTES);
        cudaFuncSetAttribute(k_y,      cudaFuncAttributeMaxDynamicSharedMemorySize, DSM_BYTES);
        cudaFuncSetAttribute(k_wy,     cudaFuncAttributeMaxDynamicSharedMemorySize, DSM_BYTES);
        attr_done = 1;
    }

    k_xt    <<<dim3(NN / 32, C_IN / 32, BATCH), dim3(32, 8)>>>(x);
    k_proj  <<<dim3(32, 3, BATCH), 256, DSM_BYTES>>>(w_theta, b_theta, w_phi, b_phi, w_g, b_g);
    k_scores<<<dim3(8, 32, BATCH), 256, DSM_BYTES>>>();
    k_rowfin<<<BATCH * NN / 256, 256>>>();
    k_y     <<<dim3(32, 1, BATCH), 256, DSM_BYTES>>>();
    k_wy    <<<dim3(32, 2, BATCH), 256, DSM_BYTES>>>(w_w, b_w);
    k_bnfin <<<C_IN, 256>>>(gamma, beta);
    k_final <<<(BATCH * C_IN * NN / 4 + 255) / 256, 256>>>(x, out);
}

// round 6
// speedup vs baseline: 2.9792x; 1.0679x over previous
#include <cuda_runtime.h>
#include <cuda_bf16.h>
#include <math.h>
#include <stdint.h>

#define BATCH 8
#define C_IN 256
#define C_I  128
#define NN   4096
#define MM   1024

// ---------------------------------------------------------------------------
// Scratch
// ---------------------------------------------------------------------------
__device__ float d_xT [BATCH][NN][C_IN];    // x transposed: [n][c]
__device__ float d_thT[BATCH][NN][C_I];     // theta: [n][ci]
__device__ float d_phi[BATCH][MM][C_I];     // phi pooled: [m][ci]
__device__ float d_g  [BATCH][C_I][MM];     // g pooled: [ci][m]
__device__ float d_yT [BATCH][NN][C_I];     // y: [n][ci]
__device__ float d_wy [BATCH][C_IN][NN];
__device__ float d_bns [BATCH][C_IN][128];
__device__ float d_bnss[BATCH][C_IN][128];
__device__ float d_scale[C_IN];
__device__ float d_shift[C_IN];

// ---------------------------------------------------------------------------
// helpers
// ---------------------------------------------------------------------------
__device__ __forceinline__ uint32_t smem_u32(const void* p) {
    uint32_t a;
    asm("{ .reg .u64 t; cvta.to.shared.u64 t, %1; cvt.u32.u64 %0, t; }" : "=r"(a) : "l"(p));
    return a;
}

#define LDSM_X4(r0, r1, r2, r3, addr) \
    asm volatile("ldmatrix.sync.aligned.m8n8.x4.shared.b16 {%0,%1,%2,%3}, [%4];" \
        : "=r"(r0), "=r"(r1), "=r"(r2), "=r"(r3) : "r"(addr))

#define MMA_BF16(c, a, b) \
    asm volatile("mma.sync.aligned.m16n8k16.row.col.f32.bf16.bf16.f32 " \
        "{%0,%1,%2,%3}, {%4,%5,%6,%7}, {%8,%9}, {%0,%1,%2,%3};" \
        : "+f"((c)[0]), "+f"((c)[1]), "+f"((c)[2]), "+f"((c)[3]) \
        : "r"((a)[0]), "r"((a)[1]), "r"((a)[2]), "r"((a)[3]), "r"((b)[0]), "r"((b)[1]))

// operand tile: 128 rows x 32 bf16 cols, row stride 80 bytes (conflict-free ldmatrix)
#define T_STRIDE 80
#define T_BYTES  (128 * T_STRIDE)            // 10240
#define STAGE_BYTES (4 * T_BYTES)            // Ah, Al, Bh, Bl
#define DSM_BYTES (2 * STAGE_BYTES + 256)    // plain GEMMs
#define DSM_ATTN  (128 + 2 * STAGE_BYTES + 8 * T_BYTES + 2048)  // + P tiles + redbuf
#define STG_LD 132                           // fp32 staging stride (floats)

__device__ __forceinline__ void gprefetch(float4* p, const float* __restrict__ src,
                                          int ld, int tid)
{
    #pragma unroll
    for (int i = 0; i < 4; i++) {
        int s = tid + i * 256;
        int r = s >> 3, q = s & 7;
        p[i] = *(const float4*)(src + (size_t)r * ld + q * 4);
    }
}

__device__ __forceinline__ void gstore_split(uint32_t hi, uint32_t lo,
                                             const float4* p, int tid)
{
    #pragma unroll
    for (int i = 0; i < 4; i++) {
        int s = tid + i * 256;
        int r = s >> 3, q = s & 7;
        float4 v = p[i];
        __nv_bfloat16 h0 = __float2bfloat16(v.x);
        __nv_bfloat16 h1 = __float2bfloat16(v.y);
        __nv_bfloat16 h2 = __float2bfloat16(v.z);
        __nv_bfloat16 h3 = __float2bfloat16(v.w);
        __nv_bfloat16 l0 = __float2bfloat16(v.x - __bfloat162float(h0));
        __nv_bfloat16 l1 = __float2bfloat16(v.y - __bfloat162float(h1));
        __nv_bfloat16 l2 = __float2bfloat16(v.z - __bfloat162float(h2));
        __nv_bfloat16 l3 = __float2bfloat16(v.w - __bfloat162float(h3));
        uint32_t hA = ((uint32_t)__bfloat16_as_ushort(h1) << 16) | __bfloat16_as_ushort(h0);
        uint32_t hB = ((uint32_t)__bfloat16_as_ushort(h3) << 16) | __bfloat16_as_ushort(h2);
        uint32_t lA = ((uint32_t)__bfloat16_as_ushort(l1) << 16) | __bfloat16_as_ushort(l0);
        uint32_t lB = ((uint32_t)__bfloat16_as_ushort(l3) << 16) | __bfloat16_as_ushort(l2);
        uint32_t off = (uint32_t)(r * T_STRIDE + q * 8);
        asm volatile("st.shared.v2.b32 [%0], {%1, %2};" :: "r"(hi + off), "r"(hA), "r"(hB));
        asm volatile("st.shared.v2.b32 [%0], {%1, %2};" :: "r"(lo + off), "r"(lA), "r"(lB));
    }
}

// ---------------------------------------------------------------------------
// Mainloop: C[128 x 128] += A[128 x K] * B[128 x K]^T, bf16 split-2 (3 terms).
// ---------------------------------------------------------------------------
__device__ __forceinline__ void gemm_main(const float* __restrict__ A, int ldA,
                                          const float* __restrict__ B, int ldB,
                                          int nk, float acc[4][4][4], uint32_t base)
{
    const int tid = threadIdx.x;
    const int lane = tid & 31, wid = tid >> 5;
    const int warp_m = wid >> 2, warp_n = wid & 3;

    #define TILE(s, a) (base + (uint32_t)((s) * STAGE_BYTES + (a) * T_BYTES))

    {
        float4 p0[4], p1[4];
        gprefetch(p0, A, ldA, tid);
        gprefetch(p1, B, ldB, tid);
        gstore_split(TILE(0, 0), TILE(0, 1), p0, tid);
        gstore_split(TILE(0, 2), TILE(0, 3), p1, tid);
    }
    __syncthreads();

    const int arow = warp_m * 64 + (lane & 15);
    const int brow = warp_n * 32 + (lane & 7) + ((lane >> 4) << 3);
    const uint32_t acol0 = (uint32_t)((lane >> 4) << 4);
    const uint32_t bcol0 = (uint32_t)(((lane >> 3) & 1) << 4);

    for (int ks = 0; ks < nk; ks++) {
        const int s = ks & 1;
        const bool more = (ks + 1 < nk);
        float4 pa[4], pb[4];
        if (more) {
            gprefetch(pa, A + (ks + 1) * 32, ldA, tid);
            gprefetch(pb, B + (ks + 1) * 32, ldB, tid);
        }
        const uint32_t tAh = TILE(s, 0), tAl = TILE(s, 1);
        const uint32_t tBh = TILE(s, 2), tBl = TILE(s, 3);

        #pragma unroll
        for (int kk = 0; kk < 2; kk++) {
            uint32_t ah[4][4], al[4][4], bh[4][2], bl[4][2];
            const uint32_t ka = (uint32_t)(kk * 32) + acol0;
            const uint32_t kb = (uint32_t)(kk * 32) + bcol0;
            #pragma unroll
            for (int mf = 0; mf < 4; mf++) {
                uint32_t ad = (uint32_t)(arow + mf * 16) * T_STRIDE + ka;
                LDSM_X4(ah[mf][0], ah[mf][1], ah[mf][2], ah[mf][3], tAh + ad);
                LDSM_X4(al[mf][0], al[mf][1], al[mf][2], al[mf][3], tAl + ad);
            }
            #pragma unroll
            for (int nf2 = 0; nf2 < 2; nf2++) {
                uint32_t bd = (uint32_t)(brow + nf2 * 16) * T_STRIDE + kb;
                uint32_t r0, r1, r2, r3;
                LDSM_X4(r0, r1, r2, r3, tBh + bd);
                bh[nf2 * 2][0] = r0; bh[nf2 * 2][1] = r1;
                bh[nf2 * 2 + 1][0] = r2; bh[nf2 * 2 + 1][1] = r3;
                LDSM_X4(r0, r1, r2, r3, tBl + bd);
                bl[nf2 * 2][0] = r0; bl[nf2 * 2][1] = r1;
                bl[nf2 * 2 + 1][0] = r2; bl[nf2 * 2 + 1][1] = r3;
            }
            #pragma unroll
            for (int mf = 0; mf < 4; mf++)
                #pragma unroll
                for (int nf = 0; nf < 4; nf++) {
                    MMA_BF16(acc[mf][nf], ah[mf], bh[nf]);
                    MMA_BF16(acc[mf][nf], ah[mf], bl[nf]);
                    MMA_BF16(acc[mf][nf], al[mf], bh[nf]);
                }
        }

        if (more) {
            gstore_split(TILE(s ^ 1, 0), TILE(s ^ 1, 1), pa, tid);
            gstore_split(TILE(s ^ 1, 2), TILE(s ^ 1, 3), pb, tid);
        }
        __syncthreads();
    }
    #undef TILE
}

// fragment geometry
#define FRAG_SETUP() \
    const int lane = threadIdx.x & 31, wid = threadIdx.x >> 5; \
    const int warp_m = wid >> 2, warp_n = wid & 3; \
    const int g = lane >> 2, t2 = (lane & 3) * 2; \
    (void)warp_m; (void)warp_n; (void)g; (void)t2
#define FROW(mf, h) (warp_m * 64 + (mf) * 16 + g + (h) * 8)
#define FCOL(nf)    (warp_n * 32 + (nf) * 8 + t2)

// ---------------------------------------------------------------------------
// Transpose x[b][c][n] -> xT[b][n][c]
// ---------------------------------------------------------------------------
__global__ void k_xt(const float* __restrict__ x)
{
    __shared__ float t[32][33];
    const int b = blockIdx.z, c0 = blockIdx.y * 32, n0 = blockIdx.x * 32;
    const int tx = threadIdx.x, ty = threadIdx.y;
    const float* src = x + ((size_t)b * C_IN + c0) * NN + n0;
    #pragma unroll
    for (int i = 0; i < 32; i += 8) t[ty + i][tx] = src[(size_t)(ty + i) * NN + tx];
    __syncthreads();
    #pragma unroll
    for (int i = 0; i < 32; i += 8) d_xT[b][n0 + ty + i][c0 + tx] = t[tx][ty + i];
}

// ---------------------------------------------------------------------------
// Projections: C[n][o] = xT[n][:]·W[o][:].  y=0 theta, y=1 phi(pool), y=2 g(pool)
// ---------------------------------------------------------------------------
__global__ __launch_bounds__(256) void k_proj(
    const float* __restrict__ w_theta, const float* __restrict__ b_theta,
    const float* __restrict__ w_phi,   const float* __restrict__ b_phi,
    const float* __restrict__ w_g,     const float* __restrict__ b_g)
{
    extern __shared__ char dsm[];
    const uint32_t base = (smem_u32(dsm) + 127u) & ~127u;
    const int b  = blockIdx.z;
    const int nT = blockIdx.x * 128;
    const float* Wp; const float* Bp;
    if (blockIdx.y == 0)      { Wp = w_theta; Bp = b_theta; }
    else if (blockIdx.y == 1) { Wp = w_phi;   Bp = b_phi;   }
    else                      { Wp = w_g;     Bp = b_g;     }

    float acc[4][4][4] = {};
    gemm_main(&d_xT[b][nT][0], C_IN, Wp, C_IN, C_IN / 32, acc, base);

    FRAG_SETUP();
    if (blockIdx.y == 0) {
        #pragma unroll
        for (int mf = 0; mf < 4; mf++)
            #pragma unroll
            for (int nf = 0; nf < 4; nf++) {
                int col = FCOL(nf);
                float2 bias = *(const float2*)&Bp[col];
                *(float2*)&d_thT[b][nT + FROW(mf, 0)][col] =
                    make_float2(acc[mf][nf][0] + bias.x, acc[mf][nf][1] + bias.y);
                *(float2*)&d_thT[b][nT + FROW(mf, 1)][col] =
                    make_float2(acc[mf][nf][2] + bias.x, acc[mf][nf][3] + bias.y);
            }
    } else {
        float* stg = (float*)dsm;
        #pragma unroll
        for (int mf = 0; mf < 4; mf++)
            #pragma unroll
            for (int nf = 0; nf < 4; nf++) {
                int col = FCOL(nf);
                int r0 = FROW(mf, 0), r1 = FROW(mf, 1);
                stg[col * STG_LD + r0]       = acc[mf][nf][0];
                stg[(col + 1) * STG_LD + r0] = acc[mf][nf][1];
                stg[col * STG_LD + r1]       = acc[mf][nf][2];
                stg[(col + 1) * STG_LD + r1] = acc[mf][nf][3];
            }
        __syncthreads();
        const int m0 = blockIdx.x * 32;
        const int t = threadIdx.x;
        if (blockIdx.y == 1) {
            #pragma unroll
            for (int ob = 0; ob < 4; ob++) {
                int oo = ob * 32 + (t & 31);
                #pragma unroll
                for (int i = 0; i < 4; i++) {
                    int wp = (t >> 5) + i * 8;
                    float2 a = *(const float2*)&stg[oo * STG_LD + 2 * wp];
                    float2 c = *(const float2*)&stg[oo * STG_LD + 64 + 2 * wp];
                    d_phi[b][m0 + wp][oo] = fmaxf(fmaxf(a.x, a.y), fmaxf(c.x, c.y)) + Bp[oo];
                }
            }
        } else {
            const int wp = t & 31;
            #pragma unroll
            for (int i = 0; i < 16; i++) {
                int o = (t >> 5) + i * 8;
                float2 a = *(const float2*)&stg[o * STG_LD + 2 * wp];
                float2 c = *(const float2*)&stg[o * STG_LD + 64 + 2 * wp];
                d_g[b][o][m0 + wp] = fmaxf(fmaxf(a.x, a.y), fmaxf(c.x, c.y)) + Bp[o];
            }
        }
    }
}

// ---------------------------------------------------------------------------
// Fused attention: for an n-tile of 128 rows, loop over 8 m-tiles:
//   phase A: facc = theta · phi_mtile^T  (split-2 HMMA)
//   phase B: exp in fragments, accumulate row partials, P -> smem (bf16 hi/lo)
//   phase C: yacc += P · g_mtile^T       (split-2 HMMA, A from smem)
// Epilogue: cross-warp row-sum reduction, y = yacc / rowsum -> d_yT.
// ---------------------------------------------------------------------------
__global__ __launch_bounds__(256) void k_attn()
{
    extern __shared__ char dsm[];
    char* dsma = (char*)((((uintptr_t)dsm) + 127) & ~(uintptr_t)127);
    const uint32_t base  = smem_u32(dsma);
    const uint32_t Pbase = base + 2 * STAGE_BYTES;
    float* redbuf = (float*)(dsma + 2 * STAGE_BYTES + 8 * T_BYTES);

    const int b  = blockIdx.z;
    const int nT = blockIdx.x * 128;
    const int tid = threadIdx.x;
    FRAG_SETUP();
    const int arow = warp_m * 64 + (lane & 15);
    const int brow = warp_n * 32 + (lane & 7) + ((lane >> 4) << 3);
    const uint32_t acol0 = (uint32_t)((lane >> 4) << 4);
    const uint32_t bcol0 = (uint32_t)(((lane >> 3) & 1) << 4);

    float yacc[4][4][4] = {};
    float ps[4][2] = {};

    for (int mt = 0; mt < 8; mt++) {
        const int mT = mt * 128;

        // ---- phase A: scores tile
        float facc[4][4][4] = {};
        gemm_main(&d_thT[b][nT][0], C_I, &d_phi[b][mT][0], C_I, C_I / 32, facc, base);

        // ---- phase B: exp + row partials + P to smem (chunk = warp_n)
        const uint32_t Ph = Pbase + (uint32_t)(warp_n * 2) * T_BYTES;
        const uint32_t Pl = Ph + T_BYTES;
        #pragma unroll
        for (int mf = 0; mf < 4; mf++) {
            const int r0 = FROW(mf, 0), r1 = FROW(mf, 1);
            #pragma unroll
            for (int nf = 0; nf < 4; nf++) {
                float e0 = __expf(facc[mf][nf][0]);
                float e1 = __expf(facc[mf][nf][1]);
                float e2 = __expf(facc[mf][nf][2]);
                float e3 = __expf(facc[mf][nf][3]);
                ps[mf][0] += e0 + e1;
                ps[mf][1] += e2 + e3;
                __nv_bfloat16 h0 = __float2bfloat16(e0);
                __nv_bfloat16 h1 = __float2bfloat16(e1);
                __nv_bfloat16 h2 = __float2bfloat16(e2);
                __nv_bfloat16 h3 = __float2bfloat16(e3);
                __nv_bfloat16 l0 = __float2bfloat16(e0 - __bfloat162float(h0));
                __nv_bfloat16 l1 = __float2bfloat16(e1 - __bfloat162float(h1));
                __nv_bfloat16 l2 = __float2bfloat16(e2 - __bfloat162float(h2));
                __nv_bfloat16 l3 = __float2bfloat16(e3 - __bfloat162float(h3));
                uint32_t hA = ((uint32_t)__bfloat16_as_ushort(h1) << 16) | __bfloat16_as_ushort(h0);
                uint32_t hB = ((uint32_t)__bfloat16_as_ushort(h3) << 16) | __bfloat16_as_ushort(h2);
                uint32_t lA = ((uint32_t)__bfloat16_as_ushort(l1) << 16) | __bfloat16_as_ushort(l0);
                uint32_t lB = ((uint32_t)__bfloat16_as_ushort(l3) << 16) | __bfloat16_as_ushort(l2);
                uint32_t off0 = (uint32_t)(r0 * T_STRIDE + (nf * 8 + t2) * 2);
                uint32_t off1 = (uint32_t)(r1 * T_STRIDE + (nf * 8 + t2) * 2);
                asm volatile("st.shared.b32 [%0], %1;" :: "r"(Ph + off0), "r"(hA));
                asm volatile("st.shared.b32 [%0], %1;" :: "r"(Pl + off0), "r"(lA));
                asm volatile("st.shared.b32 [%0], %1;" :: "r"(Ph + off1), "r"(hB));
                asm volatile("st.shared.b32 [%0], %1;" :: "r"(Pl + off1), "r"(lB));
            }
        }
        __syncthreads();

        // ---- phase C: yacc += P · g^T
        const float* gB = &d_g[b][0][mT];
        {
            float4 p[4];
            gprefetch(p, gB, MM, tid);
            gstore_split(base + 2 * T_BYTES, base + 3 * T_BYTES, p, tid);
        }
        __syncthreads();
        for (int kc = 0; kc < 4; kc++) {
            const int s = kc & 1;
            const bool more = (kc + 1 < 4);
            float4 pb[4];
            if (more) gprefetch(pb, gB + (kc + 1) * 32, MM, tid);
            const uint32_t tPh = Pbase + (uint32_t)(kc * 2) * T_BYTES;
            const uint32_t tPl = tPh + T_BYTES;
            const uint32_t tBh = base + (uint32_t)(s * STAGE_BYTES + 2 * T_BYTES);
            const uint32_t tBl = tBh + T_BYTES;
            #pragma unroll
            for (int kk = 0; kk < 2; kk++) {
                uint32_t ah[4][4], al[4][4], bh[4][2], bl[4][2];
                const uint32_t ka = (uint32_t)(kk * 32) + acol0;
                const uint32_t kb = (uint32_t)(kk * 32) + bcol0;
                #pragma unroll
                for (int mf = 0; mf < 4; mf++) {
                    uint32_t ad = (uint32_t)(arow + mf * 16) * T_STRIDE + ka;
                    LDSM_X4(ah[mf][0], ah[mf][1], ah[mf][2], ah[mf][3], tPh + ad);
                    LDSM_X4(al[mf][0], al[mf][1], al[mf][2], al[mf][3], tPl + ad);
                }
                #pragma unroll
                for (int nf2 = 0; nf2 < 2; nf2++) {
                    uint32_t bd = (uint32_t)(brow + nf2 * 16) * T_STRIDE + kb;
                    uint32_t r0, r1, r2, r3;
                    LDSM_X4(r0, r1, r2, r3, tBh + bd);
                    bh[nf2 * 2][0] = r0; bh[nf2 * 2][1] = r1;
                    bh[nf2 * 2 + 1][0] = r2; bh[nf2 * 2 + 1][1] = r3;
                    LDSM_X4(r0, r1, r2, r3, tBl + bd);
                    bl[nf2 * 2][0] = r0; bl[nf2 * 2][1] = r1;
                    bl[nf2 * 2 + 1][0] = r2; bl[nf2 * 2 + 1][1] = r3;
                }
                #pragma unroll
                for (int mf = 0; mf < 4; mf++)
                    #pragma unroll
                    for (int nf = 0; nf < 4; nf++) {
                        MMA_BF16(yacc[mf][nf], ah[mf], bh[nf]);
                        MMA_BF16(yacc[mf][nf], ah[mf], bl[nf]);
                        MMA_BF16(yacc[mf][nf], al[mf], bh[nf]);
                    }
            }
            if (more)
                gstore_split(base + (uint32_t)((s ^ 1) * STAGE_BYTES + 2 * T_BYTES),
                             base + (uint32_t)((s ^ 1) * STAGE_BYTES + 3 * T_BYTES), pb, tid);
            __syncthreads();
        }
    }

    // ---- epilogue: row sums across warp_n, normalize, write y
    #pragma unroll
    for (int mf = 0; mf < 4; mf++)
        #pragma unroll
        for (int h = 0; h < 2; h++) {
            float v = ps[mf][h];
            v += __shfl_xor_sync(0xffffffffu, v, 1);
            v += __shfl_xor_sync(0xffffffffu, v, 2);
            if ((lane & 3) == 0) redbuf[warp_n * 128 + FROW(mf, h)] = v;
        }
    __syncthreads();
    #pragma unroll
    for (int mf = 0; mf < 4; mf++)
        #pragma unroll
        for (int h = 0; h < 2; h++) {
            int row = FROW(mf, h);
            float iv = 1.f / (redbuf[row] + redbuf[128 + row] +
                              redbuf[256 + row] + redbuf[384 + row]);
            #pragma unroll
            for (int nf = 0; nf < 4; nf++) {
                float c0 = yacc[mf][nf][2 * h]     * iv;
                float c1 = yacc[mf][nf][2 * h + 1] * iv;
                *(float2*)&d_yT[b][nT + row][FCOL(nf)] = make_float2(c0, c1);
            }
        }
}

// ---------------------------------------------------------------------------
// wy: C[c][n] = w_w[c][:]·y[n][:] + bias; fused BN partials
// ---------------------------------------------------------------------------
__global__ __launch_bounds__(256) void k_wy(const float* __restrict__ w_w,
                                            const float* __restrict__ b_w)
{
    extern __shared__ char dsm[];
    const uint32_t base = (smem_u32(dsm) + 127u) & ~127u;
    const int b  = blockIdx.z;
    const int cT = blockIdx.y * 128;
    const int nT = blockIdx.x * 128;

    float acc[4][4][4] = {};
    gemm_main(w_w + (size_t)cT * C_I, C_I, &d_yT[b][nT][0], C_I, C_I / 32, acc, base);

    FRAG_SETUP();
    const int sub = blockIdx.x * 4 + warp_n;
    #pragma unroll
    for (int mf = 0; mf < 4; mf++)
        #pragma unroll
        for (int h = 0; h < 2; h++) {
            int row = FROW(mf, h);
            int c = cT + row;
            float bias = b_w[c];
            float s = 0.f, ss = 0.f;
            #pragma unroll
            for (int nf = 0; nf < 4; nf++) {
                float c0 = acc[mf][nf][2 * h]     + bias;
                float c1 = acc[mf][nf][2 * h + 1] + bias;
                s += c0 + c1;
                ss += c0 * c0 + c1 * c1;
                *(float2*)&d_wy[b][c][nT + FCOL(nf)] = make_float2(c0, c1);
            }
            s  += __shfl_xor_sync(0xffffffffu, s, 1);
            s  += __shfl_xor_sync(0xffffffffu, s, 2);
            ss += __shfl_xor_sync(0xffffffffu, ss, 1);
            ss += __shfl_xor_sync(0xffffffffu, ss, 2);
            if ((lane & 3) == 0) { d_bns[b][c][sub] = s; d_bnss[b][c][sub] = ss; }
        }
}

// ---------------------------------------------------------------------------
// BN finalize
// ---------------------------------------------------------------------------
__global__ void k_bnfin(const float* __restrict__ gamma, const float* __restrict__ beta)
{
    const int c = blockIdx.x;
    const int t = threadIdx.x;
    float s = 0.f, ss = 0.f;
    #pragma unroll
    for (int i = 0; i < 4; i++) {
        int id = t + i * 256;
        int b = id >> 7, tile = id & 127;
        s  += d_bns [b][c][tile];
        ss += d_bnss[b][c][tile];
    }
    const int lane = t & 31, warp = t >> 5;
    #pragma unroll
    for (int o = 16; o > 0; o >>= 1) {
        s  += __shfl_xor_sync(0xffffffffu, s, o);
        ss += __shfl_xor_sync(0xffffffffu, ss, o);
    }
    __shared__ float rs[8], rss[8];
    if (lane == 0) { rs[warp] = s; rss[warp] = ss; }
    __syncthreads();
    if (t == 0) {
        float S = 0.f, SS = 0.f;
        #pragma unroll
        for (int i = 0; i < 8; i++) { S += rs[i]; SS += rss[i]; }
        const float invN = 1.f / (BATCH * NN);
        float mean = S * invN;
        float var  = SS * invN - mean * mean;
        float istd = rsqrtf(var + 1e-5f);
        float sc = gamma[c] * istd;
        d_scale[c] = sc;
        d_shift[c] = beta[c] - mean * sc;
    }
}

// ---------------------------------------------------------------------------
// out = BN(wy) + x
// ---------------------------------------------------------------------------
__global__ void k_final(const float* __restrict__ x, float* __restrict__ out)
{
    size_t i4 = (size_t)blockIdx.x * blockDim.x + threadIdx.x;
    if (i4 >= (size_t)BATCH * C_IN * NN / 4) return;
    int c = (int)((i4 >> 10) & (C_IN - 1));
    float sc = d_scale[c], sh = d_shift[c];
    float4 w  = ((const float4*)&d_wy[0][0][0])[i4];
    float4 xv = ((const float4*)x)[i4];
    float4 o;
    o.x = w.x * sc + sh + xv.x;
    o.y = w.y * sc + sh + xv.y;
    o.z = w.z * sc + sh + xv.z;
    o.w = w.w * sc + sh + xv.w;
    ((float4*)out)[i4] = o;
}

// ---------------------------------------------------------------------------
extern "C" void kernel_launch(void* const* d_in, const int* in_sizes, int n_in,
                              void* d_out, int out_size)
{
    const float* x       = (const float*)d_in[0];
    const float* w_g     = (const float*)d_in[1];
    const float* b_g     = (const float*)d_in[2];
    const float* w_theta = (const float*)d_in[3];
    const float* b_theta = (const float*)d_in[4];
    const float* w_phi   = (const float*)d_in[5];
    const float* b_phi   = (const float*)d_in[6];
    const float* w_w     = (const float*)d_in[7];
    const float* b_w     = (const float*)d_in[8];
    const float* gamma   = (const float*)d_in[9];
    const float* beta    = (const float*)d_in[10];
    float* out = (float*)d_out;

    cudaFuncSetAttribute(k_proj, cudaFuncAttributeMaxDynamicSharedMemorySize, DSM_BYTES);
    cudaFuncSetAttribute(k_attn, cudaFuncAttributeMaxDynamicSharedMemorySize, DSM_ATTN);
    cudaFuncSetAttribute(k_wy,   cudaFuncAttributeMaxDynamicSharedMemorySize, DSM_BYTES);

    k_xt   <<<dim3(NN / 32, C_IN / 32, BATCH), dim3(32, 8)>>>(x);
    k_proj <<<dim3(32, 3, BATCH), 256, DSM_BYTES>>>(w_theta, b_theta, w_phi, b_phi, w_g, b_g);
    k_attn <<<dim3(32, 1, BATCH), 256, DSM_ATTN>>>();
    k_wy   <<<dim3(32, 2, BATCH), 256, DSM_BYTES>>>(w_w, b_w);
    k_bnfin<<<C_IN, 256>>>(gamma, beta);
    k_final<<<(BATCH * C_IN * NN / 4 + 255) / 256, 256>>>(x, out);
}

// round 7
// speedup vs baseline: 3.5028x; 1.1757x over previous
#include <cuda_runtime.h>
#include <cuda_bf16.h>
#include <math.h>
#include <stdint.h>

#define BATCH 8
#define C_IN 256
#define C_I  128
#define NN   4096
#define MM   1024

// ---------------------------------------------------------------------------
// Scratch: bf16 hi/lo operand planes + fp32 outputs
// ---------------------------------------------------------------------------
__device__ __align__(16) __nv_bfloat16 d_xTh[BATCH][NN][C_IN];
__device__ __align__(16) __nv_bfloat16 d_xTl[BATCH][NN][C_IN];
__device__ __align__(16) __nv_bfloat16 d_thh[BATCH][NN][C_I];
__device__ __align__(16) __nv_bfloat16 d_thl[BATCH][NN][C_I];
__device__ __align__(16) __nv_bfloat16 d_phh[BATCH][MM][C_I];
__device__ __align__(16) __nv_bfloat16 d_phl[BATCH][MM][C_I];
__device__ __align__(16) __nv_bfloat16 d_gh [BATCH][C_I][MM];
__device__ __align__(16) __nv_bfloat16 d_gl [BATCH][C_I][MM];
__device__ __align__(16) __nv_bfloat16 d_yh [BATCH][NN][C_I];
__device__ __align__(16) __nv_bfloat16 d_yl [BATCH][NN][C_I];
__device__ __align__(16) __nv_bfloat16 d_wthh[C_I][C_IN], d_wthl[C_I][C_IN];
__device__ __align__(16) __nv_bfloat16 d_wphh[C_I][C_IN], d_wphl[C_I][C_IN];
__device__ __align__(16) __nv_bfloat16 d_wgh [C_I][C_IN], d_wgl [C_I][C_IN];
__device__ __align__(16) __nv_bfloat16 d_wwh [C_IN][C_I], d_wwl [C_IN][C_I];

__device__ float d_wy [BATCH][C_IN][NN];
__device__ float d_bns [BATCH][C_IN][128];
__device__ float d_bnss[BATCH][C_IN][128];
__device__ float d_scale[C_IN];
__device__ float d_shift[C_IN];

// ---------------------------------------------------------------------------
// helpers
// ---------------------------------------------------------------------------
__device__ __forceinline__ uint32_t smem_u32(const void* p) {
    uint32_t a;
    asm("{ .reg .u64 t; cvta.to.shared.u64 t, %1; cvt.u32.u64 %0, t; }" : "=r"(a) : "l"(p));
    return a;
}

#define LDSM_X4(r0, r1, r2, r3, addr) \
    asm volatile("ldmatrix.sync.aligned.m8n8.x4.shared.b16 {%0,%1,%2,%3}, [%4];" \
        : "=r"(r0), "=r"(r1), "=r"(r2), "=r"(r3) : "r"(addr))

#define MMA_BF16(c, a, b) \
    asm volatile("mma.sync.aligned.m16n8k16.row.col.f32.bf16.bf16.f32 " \
        "{%0,%1,%2,%3}, {%4,%5,%6,%7}, {%8,%9}, {%0,%1,%2,%3};" \
        : "+f"((c)[0]), "+f"((c)[1]), "+f"((c)[2]), "+f"((c)[3]) \
        : "r"((a)[0]), "r"((a)[1]), "r"((a)[2]), "r"((a)[3]), "r"((b)[0]), "r"((b)[1]))

#define CP_COMMIT()  asm volatile("cp.async.commit_group;" ::: "memory")
#define CP_WAIT(n)   asm volatile("cp.async.wait_group %0;" :: "n"(n) : "memory")

// split fp32 pair -> packed bf16 hi (return) and lo (out-param)
__device__ __forceinline__ uint32_t pack2(float a, float b, uint32_t& lo)
{
    __nv_bfloat16 ha = __float2bfloat16(a), hb = __float2bfloat16(b);
    __nv_bfloat16 la = __float2bfloat16(a - __bfloat162float(ha));
    __nv_bfloat16 lb = __float2bfloat16(b - __bfloat162float(hb));
    lo = ((uint32_t)__bfloat16_as_ushort(lb) << 16) | __bfloat16_as_ushort(la);
    return ((uint32_t)__bfloat16_as_ushort(hb) << 16) | __bfloat16_as_ushort(ha);
}

__device__ __forceinline__ void split1(float v, __nv_bfloat16& h, __nv_bfloat16& l)
{
    h = __float2bfloat16(v);
    l = __float2bfloat16(v - __bfloat162float(h));
}

// operand tile: 128 rows x 32 bf16 cols, row stride 80 B (conflict-free ldmatrix;
// 80 = 5*16 keeps every chunk 16B-aligned for cp.async)
#define T_STRIDE 80
#define T_BYTES  (128 * T_STRIDE)            // 10240
#define DSM_GEMM (3 * 4 * T_BYTES + 128)     // 3 stages x (Ah,Al,Bh,Bl)
#define STG_LD   132                         // fp32 staging stride (floats)

// async copy one 128x32 bf16 tile (2 chunks of 16B per thread)
__device__ __forceinline__ void casync_tile(uint32_t dst, const __nv_bfloat16* __restrict__ src,
                                            int ld, int tid)
{
    #pragma unroll
    for (int i = 0; i < 2; i++) {
        int c = tid * 2 + i;
        int r = c >> 2, q = c & 3;
        const __nv_bfloat16* gp = src + (size_t)r * ld + q * 8;
        uint32_t sp = dst + (uint32_t)(r * T_STRIDE + q * 16);
        asm volatile("cp.async.cg.shared.global [%0], [%1], 16;" :: "r"(sp), "l"(gp) : "memory");
    }
}

// one 32-K chunk of split-2 HMMA: 3 terms (hh + hl + lh)
__device__ __forceinline__ void mma_chunk(uint32_t tAh, uint32_t tAl, uint32_t tBh, uint32_t tBl,
                                          float acc[4][4][4],
                                          int arow, int brow, uint32_t acol0, uint32_t bcol0)
{
    #pragma unroll
    for (int kk = 0; kk < 2; kk++) {
        uint32_t ah[4][4], al[4][4], bh[4][2], bl[4][2];
        const uint32_t ka = (uint32_t)(kk * 32) + acol0;
        const uint32_t kb = (uint32_t)(kk * 32) + bcol0;
        #pragma unroll
        for (int mf = 0; mf < 4; mf++) {
            uint32_t ad = (uint32_t)(arow + mf * 16) * T_STRIDE + ka;
            LDSM_X4(ah[mf][0], ah[mf][1], ah[mf][2], ah[mf][3], tAh + ad);
            LDSM_X4(al[mf][0], al[mf][1], al[mf][2], al[mf][3], tAl + ad);
        }
        #pragma unroll
        for (int nf2 = 0; nf2 < 2; nf2++) {
            uint32_t bd = (uint32_t)(brow + nf2 * 16) * T_STRIDE + kb;
            uint32_t r0, r1, r2, r3;
            LDSM_X4(r0, r1, r2, r3, tBh + bd);
            bh[nf2 * 2][0] = r0; bh[nf2 * 2][1] = r1;
            bh[nf2 * 2 + 1][0] = r2; bh[nf2 * 2 + 1][1] = r3;
            LDSM_X4(r0, r1, r2, r3, tBl + bd);
            bl[nf2 * 2][0] = r0; bl[nf2 * 2][1] = r1;
            bl[nf2 * 2 + 1][0] = r2; bl[nf2 * 2 + 1][1] = r3;
        }
        #pragma unroll
        for (int mf = 0; mf < 4; mf++)
            #pragma unroll
            for (int nf = 0; nf < 4; nf++) {
                MMA_BF16(acc[mf][nf], ah[mf], bh[nf]);
                MMA_BF16(acc[mf][nf], ah[mf], bl[nf]);
                MMA_BF16(acc[mf][nf], al[mf], bh[nf]);
            }
    }
}

// ---------------------------------------------------------------------------
// Streamed GEMM: C[128x128] += A[128xK] B[128xK]^T, 3-stage cp.async ring.
// ---------------------------------------------------------------------------
__device__ __forceinline__ void gemm_stream(
    const __nv_bfloat16* __restrict__ Ah, const __nv_bfloat16* __restrict__ Al, int ldA,
    const __nv_bfloat16* __restrict__ Bh, const __nv_bfloat16* __restrict__ Bl, int ldB,
    int nk, float acc[4][4][4], uint32_t base, int tid,
    int arow, int brow, uint32_t acol0, uint32_t bcol0)
{
    __syncthreads();
    #pragma unroll
    for (int s = 0; s < 2; s++) {
        uint32_t st = base + (uint32_t)(s * 4 * T_BYTES);
        casync_tile(st,               Ah + s * 32, ldA, tid);
        casync_tile(st + T_BYTES,     Al + s * 32, ldA, tid);
        casync_tile(st + 2 * T_BYTES, Bh + s * 32, ldB, tid);
        casync_tile(st + 3 * T_BYTES, Bl + s * 32, ldB, tid);
        CP_COMMIT();
    }
    for (int ks = 0; ks < nk; ks++) {
        if (ks == nk - 1) CP_WAIT(0); else CP_WAIT(1);
        __syncthreads();
        if (ks + 2 < nk) {
            uint32_t st = base + (uint32_t)(((ks + 2) % 3) * 4 * T_BYTES);
            casync_tile(st,               Ah + (ks + 2) * 32, ldA, tid);
            casync_tile(st + T_BYTES,     Al + (ks + 2) * 32, ldA, tid);
            casync_tile(st + 2 * T_BYTES, Bh + (ks + 2) * 32, ldB, tid);
            casync_tile(st + 3 * T_BYTES, Bl + (ks + 2) * 32, ldB, tid);
            CP_COMMIT();
        }
        uint32_t st = base + (uint32_t)((ks % 3) * 4 * T_BYTES);
        mma_chunk(st, st + T_BYTES, st + 2 * T_BYTES, st + 3 * T_BYTES,
                  acc, arow, brow, acol0, bcol0);
    }
}

// ---------------------------------------------------------------------------
// A-resident GEMM (attn): A tiles already in smem; B streamed, 2-stage. nk=4.
// ---------------------------------------------------------------------------
__device__ __forceinline__ void gemm_ares(
    uint32_t aTiles,
    const __nv_bfloat16* __restrict__ Bh, const __nv_bfloat16* __restrict__ Bl, int ldB,
    uint32_t stg, float acc[4][4][4], int tid,
    int arow, int brow, uint32_t acol0, uint32_t bcol0)
{
    __syncthreads();
    casync_tile(stg,           Bh, ldB, tid);
    casync_tile(stg + T_BYTES, Bl, ldB, tid);
    CP_COMMIT();
    #pragma unroll
    for (int kc = 0; kc < 4; kc++) {
        if (kc < 3) {
            uint32_t s = stg + (uint32_t)(((kc + 1) & 1) * 2 * T_BYTES);
            casync_tile(s,           Bh + (kc + 1) * 32, ldB, tid);
            casync_tile(s + T_BYTES, Bl + (kc + 1) * 32, ldB, tid);
            CP_COMMIT();
            CP_WAIT(1);
        } else {
            CP_WAIT(0);
        }
        __syncthreads();
        uint32_t sb = stg + (uint32_t)((kc & 1) * 2 * T_BYTES);
        mma_chunk(aTiles + (uint32_t)(kc * 2) * T_BYTES,
                  aTiles + (uint32_t)(kc * 2 + 1) * T_BYTES,
                  sb, sb + T_BYTES, acc, arow, brow, acol0, bcol0);
        __syncthreads();
    }
}

// fragment geometry
#define FRAG_SETUP() \
    const int lane = threadIdx.x & 31, wid = threadIdx.x >> 5; \
    const int warp_m = wid >> 2, warp_n = wid & 3; \
    const int g = lane >> 2, t2 = (lane & 3) * 2; \
    (void)warp_m; (void)warp_n; (void)g; (void)t2
#define FROW(mf, h) (warp_m * 64 + (mf) * 16 + g + (h) * 8)
#define FCOL(nf)    (warp_n * 32 + (nf) * 8 + t2)
#define GEOM_SETUP() \
    const int arow = warp_m * 64 + (lane & 15); \
    const int brow = warp_n * 32 + (lane & 7) + ((lane >> 4) << 3); \
    const uint32_t acol0 = (uint32_t)((lane >> 4) << 4); \
    const uint32_t bcol0 = (uint32_t)(((lane >> 3) & 1) << 4)

// ---------------------------------------------------------------------------
// Transpose + split x[b][c][n] -> xT planes [n][c]
// ---------------------------------------------------------------------------
__global__ void k_xt(const float* __restrict__ x)
{
    __shared__ float t[32][33];
    const int b = blockIdx.z, c0 = blockIdx.y * 32, n0 = blockIdx.x * 32;
    const int tx = threadIdx.x, ty = threadIdx.y;
    const float* src = x + ((size_t)b * C_IN + c0) * NN + n0;
    #pragma unroll
    for (int i = 0; i < 32; i += 8) t[ty + i][tx] = src[(size_t)(ty + i) * NN + tx];
    __syncthreads();
    #pragma unroll
    for (int i = 0; i < 32; i += 8) {
        __nv_bfloat16 h, l;
        split1(t[tx][ty + i], h, l);
        d_xTh[b][n0 + ty + i][c0 + tx] = h;
        d_xTl[b][n0 + ty + i][c0 + tx] = l;
    }
}

// ---------------------------------------------------------------------------
// Convert weights to bf16 planes (131072 elements total)
// ---------------------------------------------------------------------------
__global__ void k_wconv(const float* __restrict__ wth, const float* __restrict__ wph,
                        const float* __restrict__ wg,  const float* __restrict__ ww)
{
    int i = blockIdx.x * 256 + threadIdx.x;
    const float* src; __nv_bfloat16 *dh, *dl; int off;
    if (i < 32768)       { src = wth; dh = &d_wthh[0][0]; dl = &d_wthl[0][0]; off = i; }
    else if (i < 65536)  { src = wph; dh = &d_wphh[0][0]; dl = &d_wphl[0][0]; off = i - 32768; }
    else if (i < 98304)  { src = wg;  dh = &d_wgh[0][0];  dl = &d_wgl[0][0];  off = i - 65536; }
    else                 { src = ww;  dh = &d_wwh[0][0];  dl = &d_wwl[0][0];  off = i - 98304; }
    __nv_bfloat16 h, l;
    split1(src[off], h, l);
    dh[off] = h; dl[off] = l;
}

// ---------------------------------------------------------------------------
// Projections: C[n][o] = xT[n][:]·W[o][:].  y=0 theta, y=1 phi(pool), y=2 g(pool)
// ---------------------------------------------------------------------------
__global__ __launch_bounds__(256) void k_proj(
    const float* __restrict__ b_theta, const float* __restrict__ b_phi,
    const float* __restrict__ b_g)
{
    extern __shared__ char dsm[];
    const uint32_t base = (smem_u32(dsm) + 127u) & ~127u;
    const int b  = blockIdx.z;
    const int nT = blockIdx.x * 128;
    const __nv_bfloat16 *Wh, *Wl; const float* Bp;
    if (blockIdx.y == 0)      { Wh = &d_wthh[0][0]; Wl = &d_wthl[0][0]; Bp = b_theta; }
    else if (blockIdx.y == 1) { Wh = &d_wphh[0][0]; Wl = &d_wphl[0][0]; Bp = b_phi;   }
    else                      { Wh = &d_wgh[0][0];  Wl = &d_wgl[0][0];  Bp = b_g;     }

    FRAG_SETUP();
    GEOM_SETUP();
    const int tid = threadIdx.x;
    float acc[4][4][4] = {};
    gemm_stream(&d_xTh[b][nT][0], &d_xTl[b][nT][0], C_IN, Wh, Wl, C_IN,
                C_IN / 32, acc, base, tid, arow, brow, acol0, bcol0);

    if (blockIdx.y == 0) {
        #pragma unroll
        for (int mf = 0; mf < 4; mf++)
            #pragma unroll
            for (int nf = 0; nf < 4; nf++) {
                int col = FCOL(nf);
                float2 bias = *(const float2*)&Bp[col];
                int r0 = FROW(mf, 0), r1 = FROW(mf, 1);
                uint32_t lo, hi;
                hi = pack2(acc[mf][nf][0] + bias.x, acc[mf][nf][1] + bias.y, lo);
                *(uint32_t*)&d_thh[b][nT + r0][col] = hi;
                *(uint32_t*)&d_thl[b][nT + r0][col] = lo;
                hi = pack2(acc[mf][nf][2] + bias.x, acc[mf][nf][3] + bias.y, lo);
                *(uint32_t*)&d_thh[b][nT + r1][col] = hi;
                *(uint32_t*)&d_thl[b][nT + r1][col] = lo;
            }
    } else {
        float* stg = (float*)dsm;
        __syncthreads();           // stage buffers may still be read by other warps
        #pragma unroll
        for (int mf = 0; mf < 4; mf++)
            #pragma unroll
            for (int nf = 0; nf < 4; nf++) {
                int col = FCOL(nf);
                int r0 = FROW(mf, 0), r1 = FROW(mf, 1);
                stg[col * STG_LD + r0]       = acc[mf][nf][0];
                stg[(col + 1) * STG_LD + r0] = acc[mf][nf][1];
                stg[col * STG_LD + r1]       = acc[mf][nf][2];
                stg[(col + 1) * STG_LD + r1] = acc[mf][nf][3];
            }
        __syncthreads();
        const int m0 = blockIdx.x * 32;
        const int t = threadIdx.x;
        if (blockIdx.y == 1) {
            #pragma unroll
            for (int ob = 0; ob < 4; ob++) {
                int oo = ob * 32 + (t & 31);
                #pragma unroll
                for (int i = 0; i < 4; i++) {
                    int wp = (t >> 5) + i * 8;
                    float2 a = *(const float2*)&stg[oo * STG_LD + 2 * wp];
                    float2 c = *(const float2*)&stg[oo * STG_LD + 64 + 2 * wp];
                    float v = fmaxf(fmaxf(a.x, a.y), fmaxf(c.x, c.y)) + Bp[oo];
                    __nv_bfloat16 h, l;
                    split1(v, h, l);
                    d_phh[b][m0 + wp][oo] = h;
                    d_phl[b][m0 + wp][oo] = l;
                }
            }
        } else {
            const int wp = t & 31;
            #pragma unroll
            for (int i = 0; i < 16; i++) {
                int o = (t >> 5) + i * 8;
                float2 a = *(const float2*)&stg[o * STG_LD + 2 * wp];
                float2 c = *(const float2*)&stg[o * STG_LD + 64 + 2 * wp];
                float v = fmaxf(fmaxf(a.x, a.y), fmaxf(c.x, c.y)) + Bp[o];
                __nv_bfloat16 h, l;
                split1(v, h, l);
                d_gh[b][o][m0 + wp] = h;
                d_gl[b][o][m0 + wp] = l;
            }
        }
    }
}

// ---------------------------------------------------------------------------
// Fused attention, A-resident theta, streamed phi/g, P in smem.
// smem: [thA 81920][Bstg 40960][P 81920][red 2048]
// ---------------------------------------------------------------------------
#define ATTN_THA   0
#define ATTN_BSTG  (8 * T_BYTES)
#define ATTN_P     (ATTN_BSTG + 4 * T_BYTES)
#define ATTN_RED   (ATTN_P + 8 * T_BYTES)
#define DSM_ATTN   (ATTN_RED + 2048 + 128)

__global__ __launch_bounds__(256) void k_attn()
{
    extern __shared__ char dsm[];
    char* dsma = (char*)((((uintptr_t)dsm) + 127) & ~(uintptr_t)127);
    const uint32_t base = smem_u32(dsma);
    const uint32_t thA  = base + ATTN_THA;
    const uint32_t Bstg = base + ATTN_BSTG;
    const uint32_t Pb   = base + ATTN_P;
    float* redbuf = (float*)(dsma + ATTN_RED);

    const int b  = blockIdx.z;
    const int nT = blockIdx.x * 128;
    const int tid = threadIdx.x;
    FRAG_SETUP();
    GEOM_SETUP();

    // load theta tile (4 K-chunks x hi/lo) once
    {
        const __nv_bfloat16* Ah = &d_thh[b][nT][0];
        const __nv_bfloat16* Al = &d_thl[b][nT][0];
        #pragma unroll
        for (int kc = 0; kc < 4; kc++) {
            casync_tile(thA + (uint32_t)(kc * 2) * T_BYTES,     Ah + kc * 32, C_I, tid);
            casync_tile(thA + (uint32_t)(kc * 2 + 1) * T_BYTES, Al + kc * 32, C_I, tid);
        }
        CP_COMMIT();
        CP_WAIT(0);
        __syncthreads();
    }

    float yacc[4][4][4] = {};
    float ps[4][2] = {};

    for (int mt = 0; mt < 8; mt++) {
        const int mT = mt * 128;

        // phase A: scores
        float facc[4][4][4] = {};
        gemm_ares(thA, &d_phh[b][mT][0], &d_phl[b][mT][0], C_I,
                  Bstg, facc, tid, arow, brow, acol0, bcol0);

        // phase B: exp + row partials + P -> smem (warp_n owns chunk kc=warp_n)
        const uint32_t Ph = Pb + (uint32_t)(warp_n * 2) * T_BYTES;
        const uint32_t Pl = Ph + T_BYTES;
        #pragma unroll
        for (int mf = 0; mf < 4; mf++) {
            const int r0 = FROW(mf, 0), r1 = FROW(mf, 1);
            #pragma unroll
            for (int nf = 0; nf < 4; nf++) {
                float e0 = __expf(facc[mf][nf][0]);
                float e1 = __expf(facc[mf][nf][1]);
                float e2 = __expf(facc[mf][nf][2]);
                float e3 = __expf(facc[mf][nf][3]);
                ps[mf][0] += e0 + e1;
                ps[mf][1] += e2 + e3;
                uint32_t lo0, lo1;
                uint32_t hi0 = pack2(e0, e1, lo0);
                uint32_t hi1 = pack2(e2, e3, lo1);
                uint32_t off0 = (uint32_t)(r0 * T_STRIDE + (nf * 8 + t2) * 2);
                uint32_t off1 = (uint32_t)(r1 * T_STRIDE + (nf * 8 + t2) * 2);
                asm volatile("st.shared.b32 [%0], %1;" :: "r"(Ph + off0), "r"(hi0));
                asm volatile("st.shared.b32 [%0], %1;" :: "r"(Pl + off0), "r"(lo0));
                asm volatile("st.shared.b32 [%0], %1;" :: "r"(Ph + off1), "r"(hi1));
                asm volatile("st.shared.b32 [%0], %1;" :: "r"(Pl + off1), "r"(lo1));
            }
        }

        // phase C: yacc += P · g^T (g rows=ci, ld=MM)
        gemm_ares(Pb, &d_gh[b][0][mT], &d_gl[b][0][mT], MM,
                  Bstg, yacc, tid, arow, brow, acol0, bcol0);
    }

    // epilogue: cross-warp row sums, normalize, write y planes
    #pragma unroll
    for (int mf = 0; mf < 4; mf++)
        #pragma unroll
        for (int h = 0; h < 2; h++) {
            float v = ps[mf][h];
            v += __shfl_xor_sync(0xffffffffu, v, 1);
            v += __shfl_xor_sync(0xffffffffu, v, 2);
            if ((lane & 3) == 0) redbuf[warp_n * 128 + FROW(mf, h)] = v;
        }
    __syncthreads();
    #pragma unroll
    for (int mf = 0; mf < 4; mf++)
        #pragma unroll
        for (int h = 0; h < 2; h++) {
            int row = FROW(mf, h);
            float iv = 1.f / (redbuf[row] + redbuf[128 + row] +
                              redbuf[256 + row] + redbuf[384 + row]);
            #pragma unroll
            for (int nf = 0; nf < 4; nf++) {
                float c0 = yacc[mf][nf][2 * h]     * iv;
                float c1 = yacc[mf][nf][2 * h + 1] * iv;
                uint32_t lo, hi = pack2(c0, c1, lo);
                *(uint32_t*)&d_yh[b][nT + row][FCOL(nf)] = hi;
                *(uint32_t*)&d_yl[b][nT + row][FCOL(nf)] = lo;
            }
        }
}

// ---------------------------------------------------------------------------
// wy: C[c][n] = w_w[c][:]·y[n][:] + bias; fused BN partials
// ---------------------------------------------------------------------------
__global__ __launch_bounds__(256) void k_wy(const float* __restrict__ b_w)
{
    extern __shared__ char dsm[];
    const uint32_t base = (smem_u32(dsm) + 127u) & ~127u;
    const int b  = blockIdx.z;
    const int cT = blockIdx.y * 128;
    const int nT = blockIdx.x * 128;

    FRAG_SETUP();
    GEOM_SETUP();
    const int tid = threadIdx.x;
    float acc[4][4][4] = {};
    gemm_stream(&d_wwh[cT][0], &d_wwl[cT][0], C_I,
                &d_yh[b][nT][0], &d_yl[b][nT][0], C_I,
                C_I / 32, acc, base, tid, arow, brow, acol0, bcol0);

    const int sub = blockIdx.x * 4 + warp_n;
    #pragma unroll
    for (int mf = 0; mf < 4; mf++)
        #pragma unroll
        for (int h = 0; h < 2; h++) {
            int row = FROW(mf, h);
            int c = cT + row;
            float bias = b_w[c];
            float s = 0.f, ss = 0.f;
            #pragma unroll
            for (int nf = 0; nf < 4; nf++) {
                float c0 = acc[mf][nf][2 * h]     + bias;
                float c1 = acc[mf][nf][2 * h + 1] + bias;
                s += c0 + c1;
                ss += c0 * c0 + c1 * c1;
                *(float2*)&d_wy[b][c][nT + FCOL(nf)] = make_float2(c0, c1);
            }
            s  += __shfl_xor_sync(0xffffffffu, s, 1);
            s  += __shfl_xor_sync(0xffffffffu, s, 2);
            ss += __shfl_xor_sync(0xffffffffu, ss, 1);
            ss += __shfl_xor_sync(0xffffffffu, ss, 2);
            if ((lane & 3) == 0) { d_bns[b][c][sub] = s; d_bnss[b][c][sub] = ss; }
        }
}

// ---------------------------------------------------------------------------
// BN finalize
// ---------------------------------------------------------------------------
__global__ void k_bnfin(const float* __restrict__ gamma, const float* __restrict__ beta)
{
    const int c = blockIdx.x;
    const int t = threadIdx.x;
    float s = 0.f, ss = 0.f;
    #pragma unroll
    for (int i = 0; i < 4; i++) {
        int id = t + i * 256;
        int b = id >> 7, tile = id & 127;
        s  += d_bns [b][c][tile];
        ss += d_bnss[b][c][tile];
    }
    const int lane = t & 31, warp = t >> 5;
    #pragma unroll
    for (int o = 16; o > 0; o >>= 1) {
        s  += __shfl_xor_sync(0xffffffffu, s, o);
        ss += __shfl_xor_sync(0xffffffffu, ss, o);
    }
    __shared__ float rs[8], rss[8];
    if (lane == 0) { rs[warp] = s; rss[warp] = ss; }
    __syncthreads();
    if (t == 0) {
        float S = 0.f, SS = 0.f;
        #pragma unroll
        for (int i = 0; i < 8; i++) { S += rs[i]; SS += rss[i]; }
        const float invN = 1.f / (BATCH * NN);
        float mean = S * invN;
        float var  = SS * invN - mean * mean;
        float istd = rsqrtf(var + 1e-5f);
        float sc = gamma[c] * istd;
        d_scale[c] = sc;
        d_shift[c] = beta[c] - mean * sc;
    }
}

// ---------------------------------------------------------------------------
// out = BN(wy) + x
// ---------------------------------------------------------------------------
__global__ void k_final(const float* __restrict__ x, float* __restrict__ out)
{
    size_t i4 = (size_t)blockIdx.x * blockDim.x + threadIdx.x;
    if (i4 >= (size_t)BATCH * C_IN * NN / 4) return;
    int c = (int)((i4 >> 10) & (C_IN - 1));
    float sc = d_scale[c], sh = d_shift[c];
    float4 w  = ((const float4*)&d_wy[0][0][0])[i4];
    float4 xv = ((const float4*)x)[i4];
    float4 o;
    o.x = w.x * sc + sh + xv.x;
    o.y = w.y * sc + sh + xv.y;
    o.z = w.z * sc + sh + xv.z;
    o.w = w.w * sc + sh + xv.w;
    ((float4*)out)[i4] = o;
}

// ---------------------------------------------------------------------------
extern "C" void kernel_launch(void* const* d_in, const int* in_sizes, int n_in,
                              void* d_out, int out_size)
{
    const float* x       = (const float*)d_in[0];
    const float* w_g     = (const float*)d_in[1];
    const float* b_g     = (const float*)d_in[2];
    const float* w_theta = (const float*)d_in[3];
    const float* b_theta = (const float*)d_in[4];
    const float* w_phi   = (const float*)d_in[5];
    const float* b_phi   = (const float*)d_in[6];
    const float* w_w     = (const float*)d_in[7];
    const float* b_w     = (const float*)d_in[8];
    const float* gamma   = (const float*)d_in[9];
    const float* beta    = (const float*)d_in[10];
    float* out = (float*)d_out;

    cudaFuncSetAttribute(k_proj, cudaFuncAttributeMaxDynamicSharedMemorySize, DSM_GEMM);
    cudaFuncSetAttribute(k_attn, cudaFuncAttributeMaxDynamicSharedMemorySize, DSM_ATTN);
    cudaFuncSetAttribute(k_wy,   cudaFuncAttributeMaxDynamicSharedMemorySize, DSM_GEMM);

    k_xt   <<<dim3(NN / 32, C_IN / 32, BATCH), dim3(32, 8)>>>(x);
    k_wconv<<<512, 256>>>(w_theta, w_phi, w_g, w_w);
    k_proj <<<dim3(32, 3, BATCH), 256, DSM_GEMM>>>(b_theta, b_phi, b_g);
    k_attn <<<dim3(32, 1, BATCH), 256, DSM_ATTN>>>();
    k_wy   <<<dim3(32, 2, BATCH), 256, DSM_GEMM>>>(b_w);
    k_bnfin<<<C_IN, 256>>>(gamma, beta);
    k_final<<<(BATCH * C_IN * NN / 4 + 255) / 256, 256>>>(x, out);
}